// round 1
// baseline (speedup 1.0000x reference)
#include <cuda_runtime.h>

#define PP 6400
#define HH 80
#define WW 80
#define KC 256      // inner dim of correlation GEMM
#define CH 324      // real channels per direction
#define CP 384      // padded channel stride
#define CIE 336     // ci loop end (324 rounded up to 16)

// ---------------- scratch (static device globals; no allocs) ----------------
__device__ float g_corr0[(size_t)PP * PP];   // corr01  (P, 80, 80)
__device__ float g_corr1[(size_t)PP * PP];   // corr10 = corr01^T
__device__ float g_p1a[PP * 40 * 40];
__device__ float g_p1b[PP * 40 * 40];
__device__ float g_p2a[PP * 20 * 20];
__device__ float g_p2b[PP * 20 * 20];
__device__ float g_p3a[PP * 10 * 10];
__device__ float g_p3b[PP * 10 * 10];
__device__ float g_feat0[PP * CP];
__device__ float g_feat1[PP * CP];
__device__ float g_t1[PP * CP];
__device__ float g_t2[PP * CP];
__device__ float g_w1[9 * CIE * CP];
__device__ float g_w2[9 * CIE * CP];

// ---------------- GEMM: C[p][q] = sum_k A[k*P+p] * B[k*P+q] ----------------
// 128x128 tile, BK=16, 256 threads, 8x8 per thread.
__global__ __launch_bounds__(256) void gemm_corr(const float* __restrict__ A,
                                                 const float* __restrict__ B,
                                                 float* __restrict__ C) {
    __shared__ float As[16][128];
    __shared__ float Bs[16][128];
    const int tid = threadIdx.x;
    const int p0 = blockIdx.y * 128;
    const int q0 = blockIdx.x * 128;
    const int ty = tid >> 4;          // 0..15 -> rows ty*8
    const int tx = tid & 15;          // 0..15 -> cols tx*8
    const int lk = tid >> 5;          // 0..7
    const int lc = (tid & 31) << 2;   // 0..124

    float acc[8][8];
#pragma unroll
    for (int i = 0; i < 8; i++)
#pragma unroll
        for (int j = 0; j < 8; j++) acc[i][j] = 0.f;

    const float* Ap = A + (size_t)lk * PP + p0 + lc;
    const float* Bp = B + (size_t)lk * PP + q0 + lc;

    for (int k0 = 0; k0 < KC; k0 += 16) {
        float4 a0 = *(const float4*)(Ap + (size_t)k0 * PP);
        float4 a1 = *(const float4*)(Ap + (size_t)(k0 + 8) * PP);
        float4 b0 = *(const float4*)(Bp + (size_t)k0 * PP);
        float4 b1 = *(const float4*)(Bp + (size_t)(k0 + 8) * PP);
        __syncthreads();
        *(float4*)&As[lk][lc]     = a0;
        *(float4*)&As[lk + 8][lc] = a1;
        *(float4*)&Bs[lk][lc]     = b0;
        *(float4*)&Bs[lk + 8][lc] = b1;
        __syncthreads();
#pragma unroll
        for (int k = 0; k < 16; k++) {
            float a[8], b[8];
            *(float4*)&a[0] = *(const float4*)&As[k][ty * 8];
            *(float4*)&a[4] = *(const float4*)&As[k][ty * 8 + 4];
            *(float4*)&b[0] = *(const float4*)&Bs[k][tx * 8];
            *(float4*)&b[4] = *(const float4*)&Bs[k][tx * 8 + 4];
#pragma unroll
            for (int i = 0; i < 8; i++)
#pragma unroll
                for (int j = 0; j < 8; j++)
                    acc[i][j] = fmaf(a[i], b[j], acc[i][j]);
        }
    }
#pragma unroll
    for (int i = 0; i < 8; i++) {
        float* Cr = C + (size_t)(p0 + ty * 8 + i) * PP + q0 + tx * 8;
        *(float4*)Cr       = make_float4(acc[i][0], acc[i][1], acc[i][2], acc[i][3]);
        *(float4*)(Cr + 4) = make_float4(acc[i][4], acc[i][5], acc[i][6], acc[i][7]);
    }
}

// ---------------- transpose 6400x6400 ----------------
__global__ void transpose_k(const float* __restrict__ in, float* __restrict__ out) {
    __shared__ float t[32][33];
    const int bx = blockIdx.x * 32, by = blockIdx.y * 32;
    const int txx = threadIdx.x;
#pragma unroll
    for (int r = threadIdx.y; r < 32; r += 8)
        t[r][txx] = in[(size_t)(by + r) * PP + bx + txx];
    __syncthreads();
#pragma unroll
    for (int r = threadIdx.y; r < 32; r += 8)
        out[(size_t)(bx + r) * PP + by + txx] = t[txx][r];
}

// ---------------- 2x2 average pool ----------------
__global__ void pool2(const float* __restrict__ in, float* __restrict__ out,
                      int h, int w) {
    const int h2 = h >> 1, w2 = w >> 1;
    const long gid = (long)blockIdx.x * blockDim.x + threadIdx.x;
    const long tot = (long)PP * h2 * w2;
    if (gid >= tot) return;
    const int x = (int)(gid % w2);
    long t = gid / w2;
    const int y = (int)(t % h2);
    const int p = (int)(t / h2);
    const float* m = in + (size_t)p * h * w + (size_t)(2 * y) * w + 2 * x;
    out[gid] = 0.25f * (m[0] + m[1] + m[w] + m[w + 1]);
}

// ---------------- pyramid lookup ----------------
// one block per p; channels: lvl*81 + (dx+4)*9 + (dy+4)
__global__ void lookup_k(const float* __restrict__ L0, const float* __restrict__ L1,
                         const float* __restrict__ L2, const float* __restrict__ L3,
                         float* __restrict__ feat) {
    const int p = blockIdx.x;
    const int px = p % WW, py = p / WW;
    for (int ch = threadIdx.x; ch < CP; ch += blockDim.x) {
        float v = 0.f;
        if (ch < CH) {
            const int lvl = ch / 81;
            const int off = ch % 81;
            const int dx = off / 9 - 4;
            const int dy = off % 9 - 4;
            const float* base;
            int hl;
            switch (lvl) {
                case 0: base = L0; hl = 80; break;
                case 1: base = L1; hl = 40; break;
                case 2: base = L2; hl = 20; break;
                default: base = L3; hl = 10; break;
            }
            const int wl = hl;
            const float s = (float)(1 << lvl);
            const float cx = (2.f * px + 1.f) / (2.f * s) - 0.5f + (float)dx;
            const float cy = (2.f * py + 1.f) / (2.f * s) - 0.5f + (float)dy;
            const float x0f = floorf(cx), y0f = floorf(cy);
            const int ix = (int)x0f, iy = (int)y0f;
            const float fx = cx - x0f, fy = cy - y0f;
            const float* m = base + (size_t)p * hl * wl;
            float v00 = 0.f, v10 = 0.f, v01 = 0.f, v11 = 0.f;
            const bool xv0 = (ix >= 0) & (ix < wl);
            const bool xv1 = (ix + 1 >= 0) & (ix + 1 < wl);
            const bool yv0 = (iy >= 0) & (iy < hl);
            const bool yv1 = (iy + 1 >= 0) & (iy + 1 < hl);
            if (yv0) {
                if (xv0) v00 = m[iy * wl + ix];
                if (xv1) v10 = m[iy * wl + ix + 1];
            }
            if (yv1) {
                if (xv0) v01 = m[(iy + 1) * wl + ix];
                if (xv1) v11 = m[(iy + 1) * wl + ix + 1];
            }
            v = v00 * (1.f - fx) * (1.f - fy) + v10 * fx * (1.f - fy)
              + v01 * (1.f - fx) * fy + v11 * fx * fy;
        }
        feat[(size_t)p * CP + ch] = v;
    }
}

// ---------------- weight repack: (3,3,324,324) HWIO -> [tap][ci(336)][co(384)] ----------------
__global__ void repack_w(const float* __restrict__ w, float* __restrict__ wp) {
    const int id = blockIdx.x * blockDim.x + threadIdx.x;
    if (id >= 9 * CIE * CP) return;
    const int co = id % CP;
    const int t = id / CP;
    const int ci = t % CIE;
    const int tap = t / CIE;
    wp[id] = (ci < CH && co < CH) ? w[((size_t)(tap * CH + ci)) * CH + co] : 0.f;
}

// ---------------- 3x3 conv as implicit GEMM ----------------
// M=6400 pixels (BM=128), N=384 co (BN=64), K = 9 taps x 336 ci (BK=16)
// 256 threads, 8x4 per thread. Epilogue: relu(acc + bias) [+ residual]
template <int ADD_RES>
__global__ __launch_bounds__(256) void conv3x3_k(const float* __restrict__ X,
                                                 const float* __restrict__ Wt,
                                                 const float* __restrict__ bias,
                                                 const float* __restrict__ res,
                                                 float* __restrict__ Y) {
    __shared__ float As[16][128];
    __shared__ float Bs[16][64];
    const int tid = threadIdx.x;
    const int p0 = blockIdx.x * 128;
    const int c0 = blockIdx.y * 64;
    const int ty = tid >> 4;         // 0..15 -> rows ty*8, also B-load k row
    const int tx = tid & 15;         // 0..15 -> cols tx*4, also B-load col group
    const int ai = tid >> 1;         // A-load pixel 0..127
    const int akg = (tid & 1) * 8;   // A-load ci sub-offset {0,8}
    const int p = p0 + ai;
    const int py = p / WW, px = p % WW;

    float acc[8][4];
#pragma unroll
    for (int i = 0; i < 8; i++)
#pragma unroll
        for (int j = 0; j < 4; j++) acc[i][j] = 0.f;

    for (int tap = 0; tap < 9; tap++) {
        const int dy = tap / 3 - 1, dx = tap % 3 - 1;
        const bool valid = ((unsigned)(py + dy) < (unsigned)HH) &&
                           ((unsigned)(px + dx) < (unsigned)WW);
        const float* src = X + (size_t)(p + dy * WW + dx) * CP;
        const float* wsrc = Wt + (size_t)(tap * CIE) * CP + c0;
        for (int k0 = 0; k0 < CIE; k0 += 16) {
            float4 a0 = make_float4(0.f, 0.f, 0.f, 0.f);
            float4 a1 = a0;
            if (valid) {
                a0 = *(const float4*)(src + k0 + akg);
                a1 = *(const float4*)(src + k0 + akg + 4);
            }
            float4 b0 = *(const float4*)(wsrc + (size_t)(k0 + ty) * CP + tx * 4);
            __syncthreads();
            As[akg + 0][ai] = a0.x; As[akg + 1][ai] = a0.y;
            As[akg + 2][ai] = a0.z; As[akg + 3][ai] = a0.w;
            As[akg + 4][ai] = a1.x; As[akg + 5][ai] = a1.y;
            As[akg + 6][ai] = a1.z; As[akg + 7][ai] = a1.w;
            *(float4*)&Bs[ty][tx * 4] = b0;
            __syncthreads();
#pragma unroll
            for (int k = 0; k < 16; k++) {
                float a[8], b[4];
                *(float4*)&a[0] = *(const float4*)&As[k][ty * 8];
                *(float4*)&a[4] = *(const float4*)&As[k][ty * 8 + 4];
                *(float4*)&b[0] = *(const float4*)&Bs[k][tx * 4];
#pragma unroll
                for (int i = 0; i < 8; i++)
#pragma unroll
                    for (int j = 0; j < 4; j++)
                        acc[i][j] = fmaf(a[i], b[j], acc[i][j]);
            }
        }
    }
    const int c = c0 + tx * 4;
    float bv[4];
#pragma unroll
    for (int j = 0; j < 4; j++) bv[j] = (c + j < CH) ? bias[c + j] : 0.f;
#pragma unroll
    for (int i = 0; i < 8; i++) {
        const int pr = p0 + ty * 8 + i;
        float o[4];
#pragma unroll
        for (int j = 0; j < 4; j++) {
            float v = fmaxf(acc[i][j] + bv[j], 0.f);
            if (ADD_RES) v += res[(size_t)pr * CP + c + j];
            o[j] = v;
        }
        *(float4*)&Y[(size_t)pr * CP + c] = make_float4(o[0], o[1], o[2], o[3]);
    }
}

// ---------------- LayerNorm over 324 channels + NHWC -> NCHW store ----------------
__global__ __launch_bounds__(256) void ln_k(const float* __restrict__ Yin,
                                            const float* __restrict__ g,
                                            const float* __restrict__ bta,
                                            float* __restrict__ out, int cbase) {
    __shared__ float tile[CH][33];
    const int p0 = blockIdx.x * 32;
    const int warp = threadIdx.x >> 5, lane = threadIdx.x & 31;
#pragma unroll
    for (int r = 0; r < 4; r++) {
        const int lp = warp + r * 8;
        const float* row = Yin + (size_t)(p0 + lp) * CP;
        float vals[11];
        float s = 0.f, sq = 0.f;
#pragma unroll
        for (int j = 0; j < 11; j++) {
            const int ch = lane + j * 32;
            float v = (ch < CH) ? row[ch] : 0.f;
            vals[j] = v;
            s += v;
            sq += v * v;
        }
#pragma unroll
        for (int o = 16; o; o >>= 1) {
            s += __shfl_xor_sync(0xffffffffu, s, o);
            sq += __shfl_xor_sync(0xffffffffu, sq, o);
        }
        const float mean = s * (1.f / 324.f);
        const float var = sq * (1.f / 324.f) - mean * mean;
        const float inv = rsqrtf(var + 1e-5f);
#pragma unroll
        for (int j = 0; j < 11; j++) {
            const int ch = lane + j * 32;
            if (ch < CH)
                tile[ch][lp] = (vals[j] - mean) * inv * g[ch] + bta[ch];
        }
    }
    __syncthreads();
    const int col = threadIdx.x & 31;
    for (int ch = threadIdx.x >> 5; ch < CH; ch += 8)
        out[(size_t)(cbase + ch) * PP + p0 + col] = tile[ch][col];
}

// ---------------- launch ----------------
extern "C" void kernel_launch(void* const* d_in, const int* in_sizes, int n_in,
                              void* d_out, int out_size) {
    const float* f0  = (const float*)d_in[0];
    const float* f1  = (const float*)d_in[1];
    const float* w1  = (const float*)d_in[2];
    const float* b1  = (const float*)d_in[3];
    const float* w2  = (const float*)d_in[4];
    const float* b2  = (const float*)d_in[5];
    const float* lng = (const float*)d_in[6];
    const float* lnb = (const float*)d_in[7];
    float* out = (float*)d_out;

    float *corr0, *corr1, *p1a, *p1b, *p2a, *p2b, *p3a, *p3b;
    float *ft0, *ft1, *t1, *t2, *wp1, *wp2;
    cudaGetSymbolAddress((void**)&corr0, g_corr0);
    cudaGetSymbolAddress((void**)&corr1, g_corr1);
    cudaGetSymbolAddress((void**)&p1a, g_p1a);
    cudaGetSymbolAddress((void**)&p1b, g_p1b);
    cudaGetSymbolAddress((void**)&p2a, g_p2a);
    cudaGetSymbolAddress((void**)&p2b, g_p2b);
    cudaGetSymbolAddress((void**)&p3a, g_p3a);
    cudaGetSymbolAddress((void**)&p3b, g_p3b);
    cudaGetSymbolAddress((void**)&ft0, g_feat0);
    cudaGetSymbolAddress((void**)&ft1, g_feat1);
    cudaGetSymbolAddress((void**)&t1, g_t1);
    cudaGetSymbolAddress((void**)&t2, g_t2);
    cudaGetSymbolAddress((void**)&wp1, g_w1);
    cudaGetSymbolAddress((void**)&wp2, g_w2);

    // 1. correlation GEMM + transpose
    gemm_corr<<<dim3(50, 50), 256>>>(f0, f1, corr0);
    transpose_k<<<dim3(200, 200), dim3(32, 8)>>>(corr0, corr1);

    // 2. pyramids (both directions)
    {
        const long t1n = (long)PP * 40 * 40, t2n = (long)PP * 20 * 20, t3n = (long)PP * 10 * 10;
        pool2<<<(unsigned)((t1n + 255) / 256), 256>>>(corr0, p1a, 80, 80);
        pool2<<<(unsigned)((t2n + 255) / 256), 256>>>(p1a, p2a, 40, 40);
        pool2<<<(unsigned)((t3n + 255) / 256), 256>>>(p2a, p3a, 20, 20);
        pool2<<<(unsigned)((t1n + 255) / 256), 256>>>(corr1, p1b, 80, 80);
        pool2<<<(unsigned)((t2n + 255) / 256), 256>>>(p1b, p2b, 40, 40);
        pool2<<<(unsigned)((t3n + 255) / 256), 256>>>(p2b, p3b, 20, 20);
    }

    // 3. lookups
    lookup_k<<<PP, 128>>>(corr0, p1a, p2a, p3a, ft0);
    lookup_k<<<PP, 128>>>(corr1, p1b, p2b, p3b, ft1);

    // 4. weight repack
    {
        const int n = 9 * CIE * CP;
        repack_w<<<(n + 255) / 256, 256>>>(w1, wp1);
        repack_w<<<(n + 255) / 256, 256>>>(w2, wp2);
    }

    // 5. branch 0: conv1 -> conv2(+res) -> LN -> out[0:324]
    conv3x3_k<0><<<dim3(50, 6), 256>>>(ft0, wp1, b1, nullptr, t1);
    conv3x3_k<1><<<dim3(50, 6), 256>>>(t1, wp2, b2, ft0, t2);
    ln_k<<<200, 256>>>(t2, lng, lnb, out, 0);

    // 6. branch 1: -> out[324:648]
    conv3x3_k<0><<<dim3(50, 6), 256>>>(ft1, wp1, b1, nullptr, t1);
    conv3x3_k<1><<<dim3(50, 6), 256>>>(t1, wp2, b2, ft1, t2);
    ln_k<<<200, 256>>>(t2, lng, lnb, out, 324);
}

// round 2
// speedup vs baseline: 1.9596x; 1.9596x over previous
#include <cuda_runtime.h>
#include <cstdint>

#define PP 6400
#define HH 80
#define WW 80
#define KC 256      // inner dim of correlation GEMM
#define CH 324      // real channels per direction
#define CP 384      // padded channel stride
#define CIE 336     // ci loop end (324 rounded up to 16)

// ---------------- scratch (static device globals; no allocs) ----------------
__device__ float g_corr0[(size_t)PP * PP];   // corr01  (P, 80, 80)
__device__ float g_corr1[(size_t)PP * PP];   // corr10 = corr01^T
__device__ float g_p1a[PP * 40 * 40];
__device__ float g_p1b[PP * 40 * 40];
__device__ float g_p2a[PP * 20 * 20];
__device__ float g_p2b[PP * 20 * 20];
__device__ float g_p3a[PP * 10 * 10];
__device__ float g_p3b[PP * 10 * 10];
__device__ float g_feat0[PP * CP];
__device__ float g_feat1[PP * CP];
__device__ float g_t1[PP * CP];
__device__ float g_t2[PP * CP];
__device__ float g_w1[9 * CIE * CP];
__device__ float g_w2[9 * CIE * CP];

// ---------------- tf32 helpers ----------------
__device__ __forceinline__ float to_tf32(float x) {
    float y;
    asm("cvt.rna.tf32.f32 %0, %1;" : "=f"(y) : "f"(x));
    return y;
}

__device__ __forceinline__ void mma_tf32(float4& c,
                                         uint32_t a0, uint32_t a1, uint32_t a2, uint32_t a3,
                                         uint32_t b0, uint32_t b1) {
    asm volatile(
        "mma.sync.aligned.m16n8k8.row.col.f32.tf32.tf32.f32 "
        "{%0,%1,%2,%3}, {%4,%5,%6,%7}, {%8,%9}, {%0,%1,%2,%3};"
        : "+f"(c.x), "+f"(c.y), "+f"(c.z), "+f"(c.w)
        : "r"(a0), "r"(a1), "r"(a2), "r"(a3), "r"(b0), "r"(b1));
}

__device__ __forceinline__ uint32_t f2u(float x) { return __float_as_uint(x); }

// ---------------- tensor-core GEMM: C[p][q] = sum_k A[k*P+p]*B[k*P+q] ----------------
// 128x128 tile, BK=16, 8 warps (2x4), warp tile 64x32 (4 m-frags x 4 n-frags)
__global__ __launch_bounds__(256) void gemm_tc(const float* __restrict__ A,
                                               const float* __restrict__ B,
                                               float* __restrict__ C) {
    __shared__ float As[16][136];   // [k][m], pad 8 -> conflict-free frag loads
    __shared__ float Bs[16][136];   // [k][n]
    const int tid = threadIdx.x;
    const int p0 = blockIdx.y * 128;
    const int q0 = blockIdx.x * 128;
    const int warp = tid >> 5, lane = tid & 31;
    const int wm = warp >> 2, wn = warp & 3;   // 2 x 4
    const int m0 = wm * 64, n0 = wn * 32;
    const int lr = lane >> 2, lc4 = lane & 3;
    const int lk = tid >> 5;               // load row 0..7
    const int lc = (tid & 31) << 2;        // load col 0..124

    float4 acc[4][4];
#pragma unroll
    for (int i = 0; i < 4; i++)
#pragma unroll
        for (int j = 0; j < 4; j++) acc[i][j] = make_float4(0.f, 0.f, 0.f, 0.f);

    const float* Ap = A + (size_t)lk * PP + p0 + lc;
    const float* Bp = B + (size_t)lk * PP + q0 + lc;

    for (int k0 = 0; k0 < KC; k0 += 16) {
        float4 a0 = *(const float4*)(Ap + (size_t)k0 * PP);
        float4 a1 = *(const float4*)(Ap + (size_t)(k0 + 8) * PP);
        float4 b0 = *(const float4*)(Bp + (size_t)k0 * PP);
        float4 b1 = *(const float4*)(Bp + (size_t)(k0 + 8) * PP);
        __syncthreads();
        As[lk][lc]     = to_tf32(a0.x); As[lk][lc + 1]     = to_tf32(a0.y);
        As[lk][lc + 2] = to_tf32(a0.z); As[lk][lc + 3]     = to_tf32(a0.w);
        As[lk + 8][lc]     = to_tf32(a1.x); As[lk + 8][lc + 1] = to_tf32(a1.y);
        As[lk + 8][lc + 2] = to_tf32(a1.z); As[lk + 8][lc + 3] = to_tf32(a1.w);
        Bs[lk][lc]     = to_tf32(b0.x); Bs[lk][lc + 1]     = to_tf32(b0.y);
        Bs[lk][lc + 2] = to_tf32(b0.z); Bs[lk][lc + 3]     = to_tf32(b0.w);
        Bs[lk + 8][lc]     = to_tf32(b1.x); Bs[lk + 8][lc + 1] = to_tf32(b1.y);
        Bs[lk + 8][lc + 2] = to_tf32(b1.z); Bs[lk + 8][lc + 3] = to_tf32(b1.w);
        __syncthreads();
#pragma unroll
        for (int ks = 0; ks < 16; ks += 8) {
            uint32_t af[4][4], bf[4][2];
#pragma unroll
            for (int i = 0; i < 4; i++) {
                const int mb = m0 + i * 16 + lr;
                af[i][0] = f2u(As[ks + lc4][mb]);
                af[i][1] = f2u(As[ks + lc4][mb + 8]);
                af[i][2] = f2u(As[ks + 4 + lc4][mb]);
                af[i][3] = f2u(As[ks + 4 + lc4][mb + 8]);
            }
#pragma unroll
            for (int j = 0; j < 4; j++) {
                const int nb = n0 + j * 8 + lr;
                bf[j][0] = f2u(Bs[ks + lc4][nb]);
                bf[j][1] = f2u(Bs[ks + 4 + lc4][nb]);
            }
#pragma unroll
            for (int i = 0; i < 4; i++)
#pragma unroll
                for (int j = 0; j < 4; j++)
                    mma_tf32(acc[i][j], af[i][0], af[i][1], af[i][2], af[i][3],
                             bf[j][0], bf[j][1]);
        }
    }
#pragma unroll
    for (int i = 0; i < 4; i++) {
        const int r = p0 + m0 + i * 16 + lr;
#pragma unroll
        for (int j = 0; j < 4; j++) {
            const int c = q0 + n0 + j * 8 + lc4 * 2;
            *(float2*)&C[(size_t)r * PP + c]       = make_float2(acc[i][j].x, acc[i][j].y);
            *(float2*)&C[(size_t)(r + 8) * PP + c] = make_float2(acc[i][j].z, acc[i][j].w);
        }
    }
}

// ---------------- transpose 6400x6400 ----------------
__global__ void transpose_k(const float* __restrict__ in, float* __restrict__ out) {
    __shared__ float t[32][33];
    const int bx = blockIdx.x * 32, by = blockIdx.y * 32;
    const int txx = threadIdx.x;
#pragma unroll
    for (int r = threadIdx.y; r < 32; r += 8)
        t[r][txx] = in[(size_t)(by + r) * PP + bx + txx];
    __syncthreads();
#pragma unroll
    for (int r = threadIdx.y; r < 32; r += 8)
        out[(size_t)(bx + r) * PP + by + txx] = t[txx][r];
}

// ---------------- 2x2 average pool ----------------
__global__ void pool2(const float* __restrict__ in, float* __restrict__ out,
                      int h, int w) {
    const int h2 = h >> 1, w2 = w >> 1;
    const long gid = (long)blockIdx.x * blockDim.x + threadIdx.x;
    const long tot = (long)PP * h2 * w2;
    if (gid >= tot) return;
    const int x = (int)(gid % w2);
    long t = gid / w2;
    const int y = (int)(t % h2);
    const int p = (int)(t / h2);
    const float* m = in + (size_t)p * h * w + (size_t)(2 * y) * w + 2 * x;
    out[gid] = 0.25f * (m[0] + m[1] + m[w] + m[w + 1]);
}

// ---------------- pyramid lookup ----------------
__global__ void lookup_k(const float* __restrict__ L0, const float* __restrict__ L1,
                         const float* __restrict__ L2, const float* __restrict__ L3,
                         float* __restrict__ feat) {
    const int p = blockIdx.x;
    const int px = p % WW, py = p / WW;
    for (int ch = threadIdx.x; ch < CP; ch += blockDim.x) {
        float v = 0.f;
        if (ch < CH) {
            const int lvl = ch / 81;
            const int off = ch % 81;
            const int dx = off / 9 - 4;
            const int dy = off % 9 - 4;
            const float* base;
            int hl;
            switch (lvl) {
                case 0: base = L0; hl = 80; break;
                case 1: base = L1; hl = 40; break;
                case 2: base = L2; hl = 20; break;
                default: base = L3; hl = 10; break;
            }
            const int wl = hl;
            const float s = (float)(1 << lvl);
            const float cx = (2.f * px + 1.f) / (2.f * s) - 0.5f + (float)dx;
            const float cy = (2.f * py + 1.f) / (2.f * s) - 0.5f + (float)dy;
            const float x0f = floorf(cx), y0f = floorf(cy);
            const int ix = (int)x0f, iy = (int)y0f;
            const float fx = cx - x0f, fy = cy - y0f;
            const float* m = base + (size_t)p * hl * wl;
            float v00 = 0.f, v10 = 0.f, v01 = 0.f, v11 = 0.f;
            const bool xv0 = (ix >= 0) & (ix < wl);
            const bool xv1 = (ix + 1 >= 0) & (ix + 1 < wl);
            const bool yv0 = (iy >= 0) & (iy < hl);
            const bool yv1 = (iy + 1 >= 0) & (iy + 1 < hl);
            if (yv0) {
                if (xv0) v00 = m[iy * wl + ix];
                if (xv1) v10 = m[iy * wl + ix + 1];
            }
            if (yv1) {
                if (xv0) v01 = m[(iy + 1) * wl + ix];
                if (xv1) v11 = m[(iy + 1) * wl + ix + 1];
            }
            v = v00 * (1.f - fx) * (1.f - fy) + v10 * fx * (1.f - fy)
              + v01 * (1.f - fx) * fy + v11 * fx * fy;
        }
        feat[(size_t)p * CP + ch] = v;
    }
}

// ---------------- weight repack: (3,3,324,324) HWIO -> [tap][ci(336)][co(384)] ----------------
__global__ void repack_w(const float* __restrict__ w, float* __restrict__ wp) {
    const int id = blockIdx.x * blockDim.x + threadIdx.x;
    if (id >= 9 * CIE * CP) return;
    const int co = id % CP;
    const int t = id / CP;
    const int ci = t % CIE;
    const int tap = t / CIE;
    wp[id] = (ci < CH && co < CH) ? w[((size_t)(tap * CH + ci)) * CH + co] : 0.f;
}

// ---------------- 3x3 conv as implicit GEMM on tensor cores ----------------
// M=6400 (BM=128), N=384 (BN=64), K=9*336 (BK=16)
// 8 warps (4x2), warp tile 32x32 (2 m-frags x 4 n-frags)
template <int ADD_RES>
__global__ __launch_bounds__(256) void conv_tc(const float* __restrict__ X,
                                               const float* __restrict__ Wt,
                                               const float* __restrict__ bias,
                                               const float* __restrict__ res,
                                               float* __restrict__ Y) {
    __shared__ float As[16][136];  // [k][m]
    __shared__ float Bs[16][72];   // [k][n]
    const int tid = threadIdx.x;
    const int p0 = blockIdx.x * 128;
    const int c0 = blockIdx.y * 64;
    const int warp = tid >> 5, lane = tid & 31;
    const int wm = warp >> 1, wn = warp & 1;  // 4 x 2
    const int m0 = wm * 32, n0 = wn * 32;
    const int lr = lane >> 2, lc4 = lane & 3;
    const int ai = tid >> 1;              // A-load pixel 0..127
    const int akg = (tid & 1) * 8;        // A-load k sub-offset {0,8}
    const int p = p0 + ai;
    const int py = p / WW, px = p % WW;
    const int brow = tid >> 4;            // B-load k row 0..15
    const int bcol = (tid & 15) * 4;      // B-load col

    float4 acc[2][4];
#pragma unroll
    for (int i = 0; i < 2; i++)
#pragma unroll
        for (int j = 0; j < 4; j++) acc[i][j] = make_float4(0.f, 0.f, 0.f, 0.f);

    for (int tap = 0; tap < 9; tap++) {
        const int dy = tap / 3 - 1, dx = tap % 3 - 1;
        const bool valid = ((unsigned)(py + dy) < (unsigned)HH) &&
                           ((unsigned)(px + dx) < (unsigned)WW);
        const float* src = X + (size_t)(p + dy * WW + dx) * CP;
        const float* wsrc = Wt + (size_t)(tap * CIE) * CP + c0;
        for (int k0 = 0; k0 < CIE; k0 += 16) {
            float4 a0 = make_float4(0.f, 0.f, 0.f, 0.f);
            float4 a1 = a0;
            if (valid) {
                a0 = *(const float4*)(src + k0 + akg);
                a1 = *(const float4*)(src + k0 + akg + 4);
            }
            float4 b = *(const float4*)(wsrc + (size_t)(k0 + brow) * CP + bcol);
            __syncthreads();
            As[akg + 0][ai] = to_tf32(a0.x); As[akg + 1][ai] = to_tf32(a0.y);
            As[akg + 2][ai] = to_tf32(a0.z); As[akg + 3][ai] = to_tf32(a0.w);
            As[akg + 4][ai] = to_tf32(a1.x); As[akg + 5][ai] = to_tf32(a1.y);
            As[akg + 6][ai] = to_tf32(a1.z); As[akg + 7][ai] = to_tf32(a1.w);
            Bs[brow][bcol]     = to_tf32(b.x); Bs[brow][bcol + 1] = to_tf32(b.y);
            Bs[brow][bcol + 2] = to_tf32(b.z); Bs[brow][bcol + 3] = to_tf32(b.w);
            __syncthreads();
#pragma unroll
            for (int ks = 0; ks < 16; ks += 8) {
                uint32_t af[2][4], bf[4][2];
#pragma unroll
                for (int i = 0; i < 2; i++) {
                    const int mb = m0 + i * 16 + lr;
                    af[i][0] = f2u(As[ks + lc4][mb]);
                    af[i][1] = f2u(As[ks + lc4][mb + 8]);
                    af[i][2] = f2u(As[ks + 4 + lc4][mb]);
                    af[i][3] = f2u(As[ks + 4 + lc4][mb + 8]);
                }
#pragma unroll
                for (int j = 0; j < 4; j++) {
                    const int nb = n0 + j * 8 + lr;
                    bf[j][0] = f2u(Bs[ks + lc4][nb]);
                    bf[j][1] = f2u(Bs[ks + 4 + lc4][nb]);
                }
#pragma unroll
                for (int i = 0; i < 2; i++)
#pragma unroll
                    for (int j = 0; j < 4; j++)
                        mma_tf32(acc[i][j], af[i][0], af[i][1], af[i][2], af[i][3],
                                 bf[j][0], bf[j][1]);
            }
        }
    }
#pragma unroll
    for (int i = 0; i < 2; i++) {
        const int r0 = p0 + m0 + i * 16 + lr;
#pragma unroll
        for (int j = 0; j < 4; j++) {
            const int c = c0 + n0 + j * 8 + lc4 * 2;
            const float bv0 = (c < CH) ? bias[c] : 0.f;
            const float bv1 = (c + 1 < CH) ? bias[c + 1] : 0.f;
            float vx = fmaxf(acc[i][j].x + bv0, 0.f);
            float vy = fmaxf(acc[i][j].y + bv1, 0.f);
            float vz = fmaxf(acc[i][j].z + bv0, 0.f);
            float vw = fmaxf(acc[i][j].w + bv1, 0.f);
            if (ADD_RES) {
                const float2 r0v = *(const float2*)&res[(size_t)r0 * CP + c];
                const float2 r1v = *(const float2*)&res[(size_t)(r0 + 8) * CP + c];
                vx += r0v.x; vy += r0v.y; vz += r1v.x; vw += r1v.y;
            }
            *(float2*)&Y[(size_t)r0 * CP + c]       = make_float2(vx, vy);
            *(float2*)&Y[(size_t)(r0 + 8) * CP + c] = make_float2(vz, vw);
        }
    }
}

// ---------------- LayerNorm over 324 channels + NHWC -> NCHW store ----------------
__global__ __launch_bounds__(256) void ln_k(const float* __restrict__ Yin,
                                            const float* __restrict__ g,
                                            const float* __restrict__ bta,
                                            float* __restrict__ out, int cbase) {
    __shared__ float tile[CH][33];
    const int p0 = blockIdx.x * 32;
    const int warp = threadIdx.x >> 5, lane = threadIdx.x & 31;
#pragma unroll
    for (int r = 0; r < 4; r++) {
        const int lp = warp + r * 8;
        const float* row = Yin + (size_t)(p0 + lp) * CP;
        float vals[11];
        float s = 0.f, sq = 0.f;
#pragma unroll
        for (int j = 0; j < 11; j++) {
            const int ch = lane + j * 32;
            float v = (ch < CH) ? row[ch] : 0.f;
            vals[j] = v;
            s += v;
            sq += v * v;
        }
#pragma unroll
        for (int o = 16; o; o >>= 1) {
            s += __shfl_xor_sync(0xffffffffu, s, o);
            sq += __shfl_xor_sync(0xffffffffu, sq, o);
        }
        const float mean = s * (1.f / 324.f);
        const float var = sq * (1.f / 324.f) - mean * mean;
        const float inv = rsqrtf(var + 1e-5f);
#pragma unroll
        for (int j = 0; j < 11; j++) {
            const int ch = lane + j * 32;
            if (ch < CH)
                tile[ch][lp] = (vals[j] - mean) * inv * g[ch] + bta[ch];
        }
    }
    __syncthreads();
    const int col = threadIdx.x & 31;
    for (int ch = threadIdx.x >> 5; ch < CH; ch += 8)
        out[(size_t)(cbase + ch) * PP + p0 + col] = tile[ch][col];
}

// ---------------- launch ----------------
extern "C" void kernel_launch(void* const* d_in, const int* in_sizes, int n_in,
                              void* d_out, int out_size) {
    const float* f0  = (const float*)d_in[0];
    const float* f1  = (const float*)d_in[1];
    const float* w1  = (const float*)d_in[2];
    const float* b1  = (const float*)d_in[3];
    const float* w2  = (const float*)d_in[4];
    const float* b2  = (const float*)d_in[5];
    const float* lng = (const float*)d_in[6];
    const float* lnb = (const float*)d_in[7];
    float* out = (float*)d_out;

    float *corr0, *corr1, *p1a, *p1b, *p2a, *p2b, *p3a, *p3b;
    float *ft0, *ft1, *t1, *t2, *wp1, *wp2;
    cudaGetSymbolAddress((void**)&corr0, g_corr0);
    cudaGetSymbolAddress((void**)&corr1, g_corr1);
    cudaGetSymbolAddress((void**)&p1a, g_p1a);
    cudaGetSymbolAddress((void**)&p1b, g_p1b);
    cudaGetSymbolAddress((void**)&p2a, g_p2a);
    cudaGetSymbolAddress((void**)&p2b, g_p2b);
    cudaGetSymbolAddress((void**)&p3a, g_p3a);
    cudaGetSymbolAddress((void**)&p3b, g_p3b);
    cudaGetSymbolAddress((void**)&ft0, g_feat0);
    cudaGetSymbolAddress((void**)&ft1, g_feat1);
    cudaGetSymbolAddress((void**)&t1, g_t1);
    cudaGetSymbolAddress((void**)&t2, g_t2);
    cudaGetSymbolAddress((void**)&wp1, g_w1);
    cudaGetSymbolAddress((void**)&wp2, g_w2);

    // 1. correlation GEMM (tensor cores, tf32) + transpose
    gemm_tc<<<dim3(50, 50), 256>>>(f0, f1, corr0);
    transpose_k<<<dim3(200, 200), dim3(32, 8)>>>(corr0, corr1);

    // 2. pyramids (both directions)
    {
        const long t1n = (long)PP * 40 * 40, t2n = (long)PP * 20 * 20, t3n = (long)PP * 10 * 10;
        pool2<<<(unsigned)((t1n + 255) / 256), 256>>>(corr0, p1a, 80, 80);
        pool2<<<(unsigned)((t2n + 255) / 256), 256>>>(p1a, p2a, 40, 40);
        pool2<<<(unsigned)((t3n + 255) / 256), 256>>>(p2a, p3a, 20, 20);
        pool2<<<(unsigned)((t1n + 255) / 256), 256>>>(corr1, p1b, 80, 80);
        pool2<<<(unsigned)((t2n + 255) / 256), 256>>>(p1b, p2b, 40, 40);
        pool2<<<(unsigned)((t3n + 255) / 256), 256>>>(p2b, p3b, 20, 20);
    }

    // 3. lookups
    lookup_k<<<PP, 128>>>(corr0, p1a, p2a, p3a, ft0);
    lookup_k<<<PP, 128>>>(corr1, p1b, p2b, p3b, ft1);

    // 4. weight repack
    {
        const int n = 9 * CIE * CP;
        repack_w<<<(n + 255) / 256, 256>>>(w1, wp1);
        repack_w<<<(n + 255) / 256, 256>>>(w2, wp2);
    }

    // 5. branch 0: conv1 -> conv2(+res) -> LN -> out[0:324]
    conv_tc<0><<<dim3(50, 6), 256>>>(ft0, wp1, b1, nullptr, t1);
    conv_tc<1><<<dim3(50, 6), 256>>>(t1, wp2, b2, ft0, t2);
    ln_k<<<200, 256>>>(t2, lng, lnb, out, 0);

    // 6. branch 1: -> out[324:648]
    conv_tc<0><<<dim3(50, 6), 256>>>(ft1, wp1, b1, nullptr, t1);
    conv_tc<1><<<dim3(50, 6), 256>>>(t1, wp2, b2, ft1, t2);
    ln_k<<<200, 256>>>(t2, lng, lnb, out, 324);
}

// round 3
// speedup vs baseline: 2.3866x; 1.2179x over previous
#include <cuda_runtime.h>
#include <cstdint>

#define PP 6400
#define HH 80
#define WW 80
#define KC 256      // inner dim of correlation GEMM
#define CH 324      // real channels per direction
#define CP 384      // padded channel stride
#define CIE 336     // ci loop end (324 rounded up to 16)

// ---------------- scratch (static device globals; no allocs) ----------------
__device__ float g_corr0[(size_t)PP * PP];   // corr01  (P, 80, 80)
__device__ float g_corr1[(size_t)PP * PP];   // corr10 = corr01^T
__device__ float g_feat[2 * PP * CP];        // lookup features, both branches
__device__ float g_t1[2 * PP * CP];
__device__ float g_t2[2 * PP * CP];
__device__ float g_w1[9 * CIE * CP];
__device__ float g_w2[9 * CIE * CP];

// ---------------- tf32 helpers ----------------
__device__ __forceinline__ float to_tf32(float x) {
    float y;
    asm("cvt.rna.tf32.f32 %0, %1;" : "=f"(y) : "f"(x));
    return y;
}

__device__ __forceinline__ void mma_tf32(float4& c,
                                         uint32_t a0, uint32_t a1, uint32_t a2, uint32_t a3,
                                         uint32_t b0, uint32_t b1) {
    asm volatile(
        "mma.sync.aligned.m16n8k8.row.col.f32.tf32.tf32.f32 "
        "{%0,%1,%2,%3}, {%4,%5,%6,%7}, {%8,%9}, {%0,%1,%2,%3};"
        : "+f"(c.x), "+f"(c.y), "+f"(c.z), "+f"(c.w)
        : "r"(a0), "r"(a1), "r"(a2), "r"(a3), "r"(b0), "r"(b1));
}

__device__ __forceinline__ uint32_t f2u(float x) { return __float_as_uint(x); }

// ---------------- tensor-core GEMM writing C and C^T ----------------
// C[p][q] = sum_k A[k*P+p]*B[k*P+q]; also C1[q][p] = C[p][q].
// 128x128 tile, BK=8 double-buffered, 8 warps (2x4), warp tile 64x32.
__global__ __launch_bounds__(256) void gemm_tc(const float* __restrict__ A,
                                               const float* __restrict__ B,
                                               float* __restrict__ C0,
                                               float* __restrict__ C1) {
    __shared__ float As[2][8][136];
    __shared__ float Bs[2][8][136];
    const int tid = threadIdx.x;
    const int p0 = blockIdx.y * 128;
    const int q0 = blockIdx.x * 128;
    const int warp = tid >> 5, lane = tid & 31;
    const int wm = warp >> 2, wn = warp & 3;   // 2 x 4
    const int m0 = wm * 64, n0 = wn * 32;
    const int lr = lane >> 2, lc4 = lane & 3;
    const int lk = tid >> 5;               // load row 0..7
    const int lc = (tid & 31) << 2;        // load col 0..124

    float4 acc[4][4];
#pragma unroll
    for (int i = 0; i < 4; i++)
#pragma unroll
        for (int j = 0; j < 4; j++) acc[i][j] = make_float4(0.f, 0.f, 0.f, 0.f);

    const float* Ap = A + (size_t)lk * PP + p0 + lc;
    const float* Bp = B + (size_t)lk * PP + q0 + lc;

    float4 av = *(const float4*)Ap;
    float4 bv = *(const float4*)Bp;
    As[0][lk][lc]     = to_tf32(av.x); As[0][lk][lc + 1] = to_tf32(av.y);
    As[0][lk][lc + 2] = to_tf32(av.z); As[0][lk][lc + 3] = to_tf32(av.w);
    Bs[0][lk][lc]     = to_tf32(bv.x); Bs[0][lk][lc + 1] = to_tf32(bv.y);
    Bs[0][lk][lc + 2] = to_tf32(bv.z); Bs[0][lk][lc + 3] = to_tf32(bv.w);
    __syncthreads();

    int buf = 0;
    for (int it = 0; it < KC / 8; ++it) {
        const bool more = (it + 1) < KC / 8;
        if (more) {
            av = *(const float4*)(Ap + (size_t)(it + 1) * 8 * PP);
            bv = *(const float4*)(Bp + (size_t)(it + 1) * 8 * PP);
        }
        // MMA on current buffer
        {
            uint32_t af[4][4], bf[4][2];
#pragma unroll
            for (int i = 0; i < 4; i++) {
                const int mb = m0 + i * 16 + lr;
                af[i][0] = f2u(As[buf][lc4][mb]);
                af[i][1] = f2u(As[buf][lc4][mb + 8]);
                af[i][2] = f2u(As[buf][lc4 + 4][mb]);
                af[i][3] = f2u(As[buf][lc4 + 4][mb + 8]);
            }
#pragma unroll
            for (int j = 0; j < 4; j++) {
                const int nb = n0 + j * 8 + lr;
                bf[j][0] = f2u(Bs[buf][lc4][nb]);
                bf[j][1] = f2u(Bs[buf][lc4 + 4][nb]);
            }
#pragma unroll
            for (int i = 0; i < 4; i++)
#pragma unroll
                for (int j = 0; j < 4; j++)
                    mma_tf32(acc[i][j], af[i][0], af[i][1], af[i][2], af[i][3],
                             bf[j][0], bf[j][1]);
        }
        if (more) {
            const int nb = buf ^ 1;
            As[nb][lk][lc]     = to_tf32(av.x); As[nb][lk][lc + 1] = to_tf32(av.y);
            As[nb][lk][lc + 2] = to_tf32(av.z); As[nb][lk][lc + 3] = to_tf32(av.w);
            Bs[nb][lk][lc]     = to_tf32(bv.x); Bs[nb][lk][lc + 1] = to_tf32(bv.y);
            Bs[nb][lk][lc + 2] = to_tf32(bv.z); Bs[nb][lk][lc + 3] = to_tf32(bv.w);
        }
        __syncthreads();
        buf ^= 1;
    }
#pragma unroll
    for (int i = 0; i < 4; i++) {
        const int r = p0 + m0 + i * 16 + lr;
#pragma unroll
        for (int j = 0; j < 4; j++) {
            const int c = q0 + n0 + j * 8 + lc4 * 2;
            *(float2*)&C0[(size_t)r * PP + c]       = make_float2(acc[i][j].x, acc[i][j].y);
            *(float2*)&C0[(size_t)(r + 8) * PP + c] = make_float2(acc[i][j].z, acc[i][j].w);
            C1[(size_t)c * PP + r]           = acc[i][j].x;
            C1[(size_t)(c + 1) * PP + r]     = acc[i][j].y;
            C1[(size_t)c * PP + r + 8]       = acc[i][j].z;
            C1[(size_t)(c + 1) * PP + r + 8] = acc[i][j].w;
        }
    }
}

// ---------------- fused pyramid + lookup ----------------
// One block per (pixel p, branch). corr row -> smem, pools in smem, 324 lookups.
__global__ __launch_bounds__(256) void pyrlook_k(const float* __restrict__ corr0,
                                                 const float* __restrict__ corr1,
                                                 float* __restrict__ feat) {
    __shared__ float L0[6400];
    __shared__ float L1[1600];
    __shared__ float L2[400];
    __shared__ float L3[100];
    const int p = blockIdx.x;
    const int br = blockIdx.y;
    const float* corr = br ? corr1 : corr0;

    const float4* src = (const float4*)(corr + (size_t)p * PP);
    float4* d0 = (float4*)L0;
    for (int i = threadIdx.x; i < 1600; i += 256) d0[i] = src[i];
    __syncthreads();
    for (int i = threadIdx.x; i < 1600; i += 256) {
        const int y = i / 40, x = i % 40;
        const float* m = L0 + y * 160 + x * 2;
        L1[i] = 0.25f * (m[0] + m[1] + m[80] + m[81]);
    }
    __syncthreads();
    for (int i = threadIdx.x; i < 400; i += 256) {
        const int y = i / 20, x = i % 20;
        const float* m = L1 + y * 80 + x * 2;
        L2[i] = 0.25f * (m[0] + m[1] + m[40] + m[41]);
    }
    __syncthreads();
    for (int i = threadIdx.x; i < 100; i += 256) {
        const int y = i / 10, x = i % 10;
        const float* m = L2 + y * 40 + x * 2;
        L3[i] = 0.25f * (m[0] + m[1] + m[20] + m[21]);
    }
    __syncthreads();

    const int px = p % WW, py = p / WW;
    float* out = feat + ((size_t)br * PP + p) * CP;
    for (int ch = threadIdx.x; ch < CP; ch += 256) {
        float v = 0.f;
        if (ch < CH) {
            const int lvl = ch / 81;
            const int off = ch % 81;
            const int dx = off / 9 - 4;
            const int dy = off % 9 - 4;
            const float* base;
            int hl;
            switch (lvl) {
                case 0: base = L0; hl = 80; break;
                case 1: base = L1; hl = 40; break;
                case 2: base = L2; hl = 20; break;
                default: base = L3; hl = 10; break;
            }
            const int wl = hl;
            const float s = (float)(1 << lvl);
            const float cx = (2.f * px + 1.f) / (2.f * s) - 0.5f + (float)dx;
            const float cy = (2.f * py + 1.f) / (2.f * s) - 0.5f + (float)dy;
            const float x0f = floorf(cx), y0f = floorf(cy);
            const int ix = (int)x0f, iy = (int)y0f;
            const float fx = cx - x0f, fy = cy - y0f;
            float v00 = 0.f, v10 = 0.f, v01 = 0.f, v11 = 0.f;
            const bool xv0 = (ix >= 0) & (ix < wl);
            const bool xv1 = (ix + 1 >= 0) & (ix + 1 < wl);
            const bool yv0 = (iy >= 0) & (iy < hl);
            const bool yv1 = (iy + 1 >= 0) & (iy + 1 < hl);
            if (yv0) {
                if (xv0) v00 = base[iy * wl + ix];
                if (xv1) v10 = base[iy * wl + ix + 1];
            }
            if (yv1) {
                if (xv0) v01 = base[(iy + 1) * wl + ix];
                if (xv1) v11 = base[(iy + 1) * wl + ix + 1];
            }
            v = v00 * (1.f - fx) * (1.f - fy) + v10 * fx * (1.f - fy)
              + v01 * (1.f - fx) * fy + v11 * fx * fy;
        }
        out[ch] = v;
    }
}

// ---------------- weight repack: (3,3,324,324) HWIO -> [tap][ci(336)][co(384)] ----------------
__global__ void repack_w(const float* __restrict__ w, float* __restrict__ wp) {
    const int id = blockIdx.x * blockDim.x + threadIdx.x;
    if (id >= 9 * CIE * CP) return;
    const int co = id % CP;
    const int t = id / CP;
    const int ci = t % CIE;
    const int tap = t / CIE;
    wp[id] = (ci < CH && co < CH) ? w[((size_t)(tap * CH + ci)) * CH + co] : 0.f;
}

// ---------------- 3x3 conv as implicit GEMM, both branches batched ----------------
// M=12800 (BM=128), N=384 (BN=128), K=9*336, BK=8 double-buffered.
// 8 warps (2x4), warp tile 64x32. Epilogue relu(acc+bias) [+res].
template <int ADD_RES>
__global__ __launch_bounds__(256) void conv_tc(const float* __restrict__ X,
                                               const float* __restrict__ Wt,
                                               const float* __restrict__ bias,
                                               const float* __restrict__ res,
                                               float* __restrict__ Y) {
    __shared__ float As[2][8][136];
    __shared__ float Bs[2][8][136];
    const int tid = threadIdx.x;
    const int p0 = blockIdx.x * 128;
    const int c0 = blockIdx.y * 128;
    const int warp = tid >> 5, lane = tid & 31;
    const int wm = warp >> 2, wn = warp & 3;   // 2 x 4
    const int m0 = wm * 64, n0 = wn * 32;
    const int lr = lane >> 2, lc4 = lane & 3;
    const int ai = tid >> 1;              // A-load pixel 0..127
    const int akg = (tid & 1) * 4;        // A-load k sub-offset {0,4}
    const int p = p0 + ai;
    const int pl = p % PP;                // branch-local pixel
    const int py = pl / WW, px = pl % WW;
    const int brow = tid >> 5;            // B-load k row 0..7
    const int bcol = (tid & 31) * 4;      // B-load col 0..124

    float4 acc[4][4];
#pragma unroll
    for (int i = 0; i < 4; i++)
#pragma unroll
        for (int j = 0; j < 4; j++) acc[i][j] = make_float4(0.f, 0.f, 0.f, 0.f);

    // loader: tap, k0
    float4 av, bv;
    {
        // tap 0: dy=-1,dx=-1
        const bool valid = ((unsigned)(py - 1) < (unsigned)HH) &&
                           ((unsigned)(px - 1) < (unsigned)WW);
        av = make_float4(0.f, 0.f, 0.f, 0.f);
        if (valid) av = *(const float4*)(X + (size_t)(p - WW - 1) * CP + akg);
        bv = *(const float4*)(Wt + (size_t)brow * CP + c0 + bcol);
    }
    As[0][akg + 0][ai] = to_tf32(av.x); As[0][akg + 1][ai] = to_tf32(av.y);
    As[0][akg + 2][ai] = to_tf32(av.z); As[0][akg + 3][ai] = to_tf32(av.w);
    Bs[0][brow][bcol]     = to_tf32(bv.x); Bs[0][brow][bcol + 1] = to_tf32(bv.y);
    Bs[0][brow][bcol + 2] = to_tf32(bv.z); Bs[0][brow][bcol + 3] = to_tf32(bv.w);
    __syncthreads();

    const int NIT = 9 * (CIE / 8);   // 378
    int tap = 0, k0 = 0, buf = 0;
    for (int it = 0; it < NIT; ++it) {
        int ntap = tap, nk0 = k0 + 8;
        if (nk0 == CIE) { nk0 = 0; ntap++; }
        const bool more = (it + 1) < NIT;
        if (more) {
            const int dy = ntap / 3 - 1, dx = ntap % 3 - 1;
            const bool valid = ((unsigned)(py + dy) < (unsigned)HH) &&
                               ((unsigned)(px + dx) < (unsigned)WW);
            av = make_float4(0.f, 0.f, 0.f, 0.f);
            if (valid)
                av = *(const float4*)(X + (size_t)(p + dy * WW + dx) * CP + nk0 + akg);
            bv = *(const float4*)(Wt + (size_t)(ntap * CIE + nk0 + brow) * CP + c0 + bcol);
        }
        // MMA on current buffer
        {
            uint32_t af[4][4], bf[4][2];
#pragma unroll
            for (int i = 0; i < 4; i++) {
                const int mb = m0 + i * 16 + lr;
                af[i][0] = f2u(As[buf][lc4][mb]);
                af[i][1] = f2u(As[buf][lc4][mb + 8]);
                af[i][2] = f2u(As[buf][lc4 + 4][mb]);
                af[i][3] = f2u(As[buf][lc4 + 4][mb + 8]);
            }
#pragma unroll
            for (int j = 0; j < 4; j++) {
                const int nb = n0 + j * 8 + lr;
                bf[j][0] = f2u(Bs[buf][lc4][nb]);
                bf[j][1] = f2u(Bs[buf][lc4 + 4][nb]);
            }
#pragma unroll
            for (int i = 0; i < 4; i++)
#pragma unroll
                for (int j = 0; j < 4; j++)
                    mma_tf32(acc[i][j], af[i][0], af[i][1], af[i][2], af[i][3],
                             bf[j][0], bf[j][1]);
        }
        if (more) {
            const int nb = buf ^ 1;
            As[nb][akg + 0][ai] = to_tf32(av.x); As[nb][akg + 1][ai] = to_tf32(av.y);
            As[nb][akg + 2][ai] = to_tf32(av.z); As[nb][akg + 3][ai] = to_tf32(av.w);
            Bs[nb][brow][bcol]     = to_tf32(bv.x); Bs[nb][brow][bcol + 1] = to_tf32(bv.y);
            Bs[nb][brow][bcol + 2] = to_tf32(bv.z); Bs[nb][brow][bcol + 3] = to_tf32(bv.w);
        }
        __syncthreads();
        buf ^= 1; tap = ntap; k0 = nk0;
    }

#pragma unroll
    for (int i = 0; i < 4; i++) {
        const int r0 = p0 + m0 + i * 16 + lr;
#pragma unroll
        for (int j = 0; j < 4; j++) {
            const int c = c0 + n0 + j * 8 + lc4 * 2;
            const float bv0 = (c < CH) ? bias[c] : 0.f;
            const float bv1 = (c + 1 < CH) ? bias[c + 1] : 0.f;
            float vx = fmaxf(acc[i][j].x + bv0, 0.f);
            float vy = fmaxf(acc[i][j].y + bv1, 0.f);
            float vz = fmaxf(acc[i][j].z + bv0, 0.f);
            float vw = fmaxf(acc[i][j].w + bv1, 0.f);
            if (ADD_RES) {
                const float2 r0v = *(const float2*)&res[(size_t)r0 * CP + c];
                const float2 r1v = *(const float2*)&res[(size_t)(r0 + 8) * CP + c];
                vx += r0v.x; vy += r0v.y; vz += r1v.x; vw += r1v.y;
            }
            *(float2*)&Y[(size_t)r0 * CP + c]       = make_float2(vx, vy);
            *(float2*)&Y[(size_t)(r0 + 8) * CP + c] = make_float2(vz, vw);
        }
    }
}

// ---------------- LayerNorm over 324 channels + NHWC -> NCHW store (both branches) ----
__global__ __launch_bounds__(256) void ln_k(const float* __restrict__ Yin,
                                            const float* __restrict__ g,
                                            const float* __restrict__ bta,
                                            float* __restrict__ out) {
    __shared__ float tile[CH][33];
    const int br = blockIdx.y;
    const int p0 = blockIdx.x * 32;
    const float* Ybr = Yin + (size_t)br * PP * CP;
    const int cbase = br * CH;
    const int warp = threadIdx.x >> 5, lane = threadIdx.x & 31;
#pragma unroll
    for (int r = 0; r < 4; r++) {
        const int lp = warp + r * 8;
        const float* row = Ybr + (size_t)(p0 + lp) * CP;
        float vals[11];
        float s = 0.f, sq = 0.f;
#pragma unroll
        for (int j = 0; j < 11; j++) {
            const int ch = lane + j * 32;
            float v = (ch < CH) ? row[ch] : 0.f;
            vals[j] = v;
            s += v;
            sq += v * v;
        }
#pragma unroll
        for (int o = 16; o; o >>= 1) {
            s += __shfl_xor_sync(0xffffffffu, s, o);
            sq += __shfl_xor_sync(0xffffffffu, sq, o);
        }
        const float mean = s * (1.f / 324.f);
        const float var = sq * (1.f / 324.f) - mean * mean;
        const float inv = rsqrtf(var + 1e-5f);
#pragma unroll
        for (int j = 0; j < 11; j++) {
            const int ch = lane + j * 32;
            if (ch < CH)
                tile[ch][lp] = (vals[j] - mean) * inv * g[ch] + bta[ch];
        }
    }
    __syncthreads();
    const int col = threadIdx.x & 31;
    for (int ch = threadIdx.x >> 5; ch < CH; ch += 8)
        out[(size_t)(cbase + ch) * PP + p0 + col] = tile[ch][col];
}

// ---------------- launch ----------------
extern "C" void kernel_launch(void* const* d_in, const int* in_sizes, int n_in,
                              void* d_out, int out_size) {
    const float* f0  = (const float*)d_in[0];
    const float* f1  = (const float*)d_in[1];
    const float* w1  = (const float*)d_in[2];
    const float* b1  = (const float*)d_in[3];
    const float* w2  = (const float*)d_in[4];
    const float* b2  = (const float*)d_in[5];
    const float* lng = (const float*)d_in[6];
    const float* lnb = (const float*)d_in[7];
    float* out = (float*)d_out;

    float *corr0, *corr1, *ft, *t1, *t2, *wp1, *wp2;
    cudaGetSymbolAddress((void**)&corr0, g_corr0);
    cudaGetSymbolAddress((void**)&corr1, g_corr1);
    cudaGetSymbolAddress((void**)&ft, g_feat);
    cudaGetSymbolAddress((void**)&t1, g_t1);
    cudaGetSymbolAddress((void**)&t2, g_t2);
    cudaGetSymbolAddress((void**)&wp1, g_w1);
    cudaGetSymbolAddress((void**)&wp2, g_w2);

    // 1. correlation GEMM writing corr01 and corr10 simultaneously
    gemm_tc<<<dim3(50, 50), 256>>>(f0, f1, corr0, corr1);

    // 2. fused pyramid + lookup (both branches in one launch)
    pyrlook_k<<<dim3(PP, 2), 256>>>(corr0, corr1, ft);

    // 3. weight repack
    {
        const int n = 9 * CIE * CP;
        repack_w<<<(n + 255) / 256, 256>>>(w1, wp1);
        repack_w<<<(n + 255) / 256, 256>>>(w2, wp2);
    }

    // 4. convs, both branches batched (M = 12800)
    conv_tc<0><<<dim3(100, 3), 256>>>(ft, wp1, b1, nullptr, t1);
    conv_tc<1><<<dim3(100, 3), 256>>>(t1, wp2, b2, ft, t2);

    // 5. LayerNorm + transpose to NCHW, both branches
    ln_k<<<dim3(200, 2), 256>>>(t2, lng, lnb, out);
}

// round 4
// speedup vs baseline: 2.8204x; 1.1818x over previous
#include <cuda_runtime.h>
#include <cstdint>

#define PP 6400
#define HH 80
#define WW 80
#define KC 256      // inner dim of correlation GEMM
#define CH 324      // real channels per direction
#define CP 384      // padded channel stride
#define CIE 336     // ci loop end (324 rounded up to 16)

// ---------------- scratch (static device globals; no allocs) ----------------
__device__ float g_corr0[(size_t)PP * PP];   // corr01  (P, 80, 80)
__device__ float g_corr1[(size_t)PP * PP];   // corr10 = corr01^T
__device__ float g_f0r[PP * KC];             // tf32-rounded f0
__device__ float g_f1r[PP * KC];             // tf32-rounded f1
__device__ float g_feat[2 * PP * CP];        // lookup features (tf32), both branches
__device__ float g_t1[2 * PP * CP];
__device__ float g_t2[2 * PP * CP];
__device__ float g_w1[9 * CIE * CP];
__device__ float g_w2[9 * CIE * CP];

// ---------------- helpers ----------------
__device__ __forceinline__ float to_tf32(float x) {
    float y;
    asm("cvt.rna.tf32.f32 %0, %1;" : "=f"(y) : "f"(x));
    return y;
}

__device__ __forceinline__ void mma_tf32(float4& c,
                                         uint32_t a0, uint32_t a1, uint32_t a2, uint32_t a3,
                                         uint32_t b0, uint32_t b1) {
    asm volatile(
        "mma.sync.aligned.m16n8k8.row.col.f32.tf32.tf32.f32 "
        "{%0,%1,%2,%3}, {%4,%5,%6,%7}, {%8,%9}, {%0,%1,%2,%3};"
        : "+f"(c.x), "+f"(c.y), "+f"(c.z), "+f"(c.w)
        : "r"(a0), "r"(a1), "r"(a2), "r"(a3), "r"(b0), "r"(b1));
}

__device__ __forceinline__ uint32_t f2u(float x) { return __float_as_uint(x); }

__device__ __forceinline__ uint32_t su32(const void* p) {
    uint32_t a;
    asm("{ .reg .u64 t; cvta.to.shared.u64 t, %1; cvt.u32.u64 %0, t; }"
        : "=r"(a) : "l"(p));
    return a;
}

__device__ __forceinline__ void cpa16(uint32_t dst, const void* src, bool v) {
    asm volatile("cp.async.cg.shared.global [%0], [%1], 16, %2;"
                 :: "r"(dst), "l"(src), "r"(v ? 16 : 0));
}
__device__ __forceinline__ void cpa_commit() {
    asm volatile("cp.async.commit_group;");
}
__device__ __forceinline__ void cpa_wait0() {
    asm volatile("cp.async.wait_group 0;");
}

// ---------------- tf32 rounding pass ----------------
__global__ void round4_k(const float4* __restrict__ in, float4* __restrict__ out) {
    const int i = blockIdx.x * blockDim.x + threadIdx.x;
    if (i < PP * KC / 4) {
        float4 v = in[i];
        out[i] = make_float4(to_tf32(v.x), to_tf32(v.y), to_tf32(v.z), to_tf32(v.w));
    }
}

// ---------------- weight repack (both weight sets; tf32-rounded) ----------------
__global__ void repack_w(const float* __restrict__ w1, const float* __restrict__ w2,
                         float* __restrict__ wp1, float* __restrict__ wp2) {
    const int id = blockIdx.x * blockDim.x + threadIdx.x;
    if (id >= 9 * CIE * CP) return;
    const float* w = blockIdx.y ? w2 : w1;
    float* wp = blockIdx.y ? wp2 : wp1;
    const int co = id % CP;
    const int t = id / CP;
    const int ci = t % CIE;
    const int tap = t / CIE;
    wp[id] = (ci < CH && co < CH) ? to_tf32(w[((size_t)(tap * CH + ci)) * CH + co]) : 0.f;
}

// ---------------- tensor-core GEMM writing C and C^T ----------------
// C[p][q] = sum_k A[k*P+p]*B[k*P+q]; also C1[q][p] = C[p][q].
// 128x128 tile, BK=16 double-buffered via cp.async; 8 warps (2x4), warp tile 64x32.
__global__ __launch_bounds__(256) void gemm_tc(const float* __restrict__ A,
                                               const float* __restrict__ B,
                                               float* __restrict__ C0,
                                               float* __restrict__ C1) {
    __shared__ float As[2][16][136];
    __shared__ float Bs[2][16][136];
    const int tid = threadIdx.x;
    const int p0 = blockIdx.y * 128;
    const int q0 = blockIdx.x * 128;
    const int warp = tid >> 5, lane = tid & 31;
    const int wm = warp >> 2, wn = warp & 3;   // 2 x 4
    const int m0 = wm * 64, n0 = wn * 32;
    const int lr = lane >> 2, lc4 = lane & 3;
    const int krow = tid >> 5;              // 0..7 (loads rows krow, krow+8)
    const int seg = (tid & 31) * 4;         // 0..124

    uint32_t asb[2], bsb[2];
    asb[0] = su32(&As[0][0][0]); asb[1] = su32(&As[1][0][0]);
    bsb[0] = su32(&Bs[0][0][0]); bsb[1] = su32(&Bs[1][0][0]);

    float4 acc[4][4];
#pragma unroll
    for (int i = 0; i < 4; i++)
#pragma unroll
        for (int j = 0; j < 4; j++) acc[i][j] = make_float4(0.f, 0.f, 0.f, 0.f);

    const float* Ap = A + p0 + seg;
    const float* Bp = B + q0 + seg;

#define GEMM_ISSUE(K0, BUF)                                                        \
    do {                                                                           \
        _Pragma("unroll")                                                          \
        for (int rr = 0; rr < 2; rr++) {                                           \
            const int r = krow + rr * 8;                                           \
            cpa16(asb[BUF] + (r * 136 + seg) * 4, Ap + (size_t)((K0) + r) * PP, true); \
            cpa16(bsb[BUF] + (r * 136 + seg) * 4, Bp + (size_t)((K0) + r) * PP, true); \
        }                                                                          \
        cpa_commit();                                                              \
    } while (0)

    GEMM_ISSUE(0, 0);
    int buf = 0;
    for (int it = 0; it < KC / 16; ++it) {
        cpa_wait0();
        __syncthreads();
        if (it + 1 < KC / 16) GEMM_ISSUE((it + 1) * 16, buf ^ 1);
#pragma unroll
        for (int ks = 0; ks < 16; ks += 8) {
            uint32_t af[4][4], bf[4][2];
#pragma unroll
            for (int i = 0; i < 4; i++) {
                const int mb = m0 + i * 16 + lr;
                af[i][0] = f2u(As[buf][ks + lc4][mb]);
                af[i][1] = f2u(As[buf][ks + lc4][mb + 8]);
                af[i][2] = f2u(As[buf][ks + lc4 + 4][mb]);
                af[i][3] = f2u(As[buf][ks + lc4 + 4][mb + 8]);
            }
#pragma unroll
            for (int j = 0; j < 4; j++) {
                const int nb = n0 + j * 8 + lr;
                bf[j][0] = f2u(Bs[buf][ks + lc4][nb]);
                bf[j][1] = f2u(Bs[buf][ks + lc4 + 4][nb]);
            }
#pragma unroll
            for (int i = 0; i < 4; i++)
#pragma unroll
                for (int j = 0; j < 4; j++)
                    mma_tf32(acc[i][j], af[i][0], af[i][1], af[i][2], af[i][3],
                             bf[j][0], bf[j][1]);
        }
        buf ^= 1;
    }
#undef GEMM_ISSUE

#pragma unroll
    for (int i = 0; i < 4; i++) {
        const int r = p0 + m0 + i * 16 + lr;
#pragma unroll
        for (int j = 0; j < 4; j++) {
            const int c = q0 + n0 + j * 8 + lc4 * 2;
            *(float2*)&C0[(size_t)r * PP + c]       = make_float2(acc[i][j].x, acc[i][j].y);
            *(float2*)&C0[(size_t)(r + 8) * PP + c] = make_float2(acc[i][j].z, acc[i][j].w);
            C1[(size_t)c * PP + r]           = acc[i][j].x;
            C1[(size_t)(c + 1) * PP + r]     = acc[i][j].y;
            C1[(size_t)c * PP + r + 8]       = acc[i][j].z;
            C1[(size_t)(c + 1) * PP + r + 8] = acc[i][j].w;
        }
    }
}

// ---------------- fused pyramid + lookup (tf32-rounded output) ----------------
__global__ __launch_bounds__(256) void pyrlook_k(const float* __restrict__ corr0,
                                                 const float* __restrict__ corr1,
                                                 float* __restrict__ feat) {
    __shared__ float L0[6400];
    __shared__ float L1[1600];
    __shared__ float L2[400];
    __shared__ float L3[100];
    const int p = blockIdx.x;
    const int br = blockIdx.y;
    const float* corr = br ? corr1 : corr0;

    const float4* src = (const float4*)(corr + (size_t)p * PP);
    float4* d0 = (float4*)L0;
    for (int i = threadIdx.x; i < 1600; i += 256) d0[i] = src[i];
    __syncthreads();
    for (int i = threadIdx.x; i < 1600; i += 256) {
        const int y = i / 40, x = i % 40;
        const float* m = L0 + y * 160 + x * 2;
        L1[i] = 0.25f * (m[0] + m[1] + m[80] + m[81]);
    }
    __syncthreads();
    for (int i = threadIdx.x; i < 400; i += 256) {
        const int y = i / 20, x = i % 20;
        const float* m = L1 + y * 80 + x * 2;
        L2[i] = 0.25f * (m[0] + m[1] + m[40] + m[41]);
    }
    __syncthreads();
    for (int i = threadIdx.x; i < 100; i += 256) {
        const int y = i / 10, x = i % 10;
        const float* m = L2 + y * 40 + x * 2;
        L3[i] = 0.25f * (m[0] + m[1] + m[20] + m[21]);
    }
    __syncthreads();

    const int px = p % WW, py = p / WW;
    float* out = feat + ((size_t)br * PP + p) * CP;
    for (int ch = threadIdx.x; ch < CP; ch += 256) {
        float v = 0.f;
        if (ch < CH) {
            const int lvl = ch / 81;
            const int off = ch % 81;
            const int dx = off / 9 - 4;
            const int dy = off % 9 - 4;
            const float* base;
            int hl;
            switch (lvl) {
                case 0: base = L0; hl = 80; break;
                case 1: base = L1; hl = 40; break;
                case 2: base = L2; hl = 20; break;
                default: base = L3; hl = 10; break;
            }
            const int wl = hl;
            const float s = (float)(1 << lvl);
            const float cx = (2.f * px + 1.f) / (2.f * s) - 0.5f + (float)dx;
            const float cy = (2.f * py + 1.f) / (2.f * s) - 0.5f + (float)dy;
            const float x0f = floorf(cx), y0f = floorf(cy);
            const int ix = (int)x0f, iy = (int)y0f;
            const float fx = cx - x0f, fy = cy - y0f;
            float v00 = 0.f, v10 = 0.f, v01 = 0.f, v11 = 0.f;
            const bool xv0 = (ix >= 0) & (ix < wl);
            const bool xv1 = (ix + 1 >= 0) & (ix + 1 < wl);
            const bool yv0 = (iy >= 0) & (iy < hl);
            const bool yv1 = (iy + 1 >= 0) & (iy + 1 < hl);
            if (yv0) {
                if (xv0) v00 = base[iy * wl + ix];
                if (xv1) v10 = base[iy * wl + ix + 1];
            }
            if (yv1) {
                if (xv0) v01 = base[(iy + 1) * wl + ix];
                if (xv1) v11 = base[(iy + 1) * wl + ix + 1];
            }
            v = v00 * (1.f - fx) * (1.f - fy) + v10 * fx * (1.f - fy)
              + v01 * (1.f - fx) * fy + v11 * fx * fy;
        }
        out[ch] = to_tf32(v);
    }
}

// ---------------- 3x3 conv as implicit GEMM, cp.async pipeline ----------------
// M=12800 (BM=128), N=384 (BN=128), K=9 taps x 336, BK=16 double-buffered.
// 8 warps (2x4), warp tile 64x32. Epilogue relu(acc+bias) [+res].
// ADD_RES==0 -> output tf32-rounded (feeds next conv); ADD_RES==1 -> raw fp32.
template <int ADD_RES>
__global__ __launch_bounds__(256) void conv_tc(const float* __restrict__ X,
                                               const float* __restrict__ Wt,
                                               const float* __restrict__ bias,
                                               const float* __restrict__ res,
                                               float* __restrict__ Y) {
    __shared__ float As[2][128][28];   // [m][k], stride 28 -> conflict-free, 16B rows
    __shared__ float Bs[2][16][136];   // [k][n]
    const int tid = threadIdx.x;
    const int p0 = blockIdx.x * 128;
    const int c0 = blockIdx.y * 128;
    const int warp = tid >> 5, lane = tid & 31;
    const int wm = warp >> 2, wn = warp & 3;   // 2 x 4
    const int m0 = wm * 64, n0 = wn * 32;
    const int lr = lane >> 2, lc4 = lane & 3;

    // A loader: rows arow, arow+64; 16-float slab split in 4 segs
    const int arow = tid >> 2;
    const int aseg = (tid & 3) * 4;
    // B loader: rows brow, brow+8; 128 cols in 32 segs
    const int brow = tid >> 5;
    const int bseg = (tid & 31) * 4;

    uint32_t asb[2], bsb[2];
    asb[0] = su32(&As[0][0][0]); asb[1] = su32(&As[1][0][0]);
    bsb[0] = su32(&Bs[0][0][0]); bsb[1] = su32(&Bs[1][0][0]);

    int apy[2], apx[2];
#pragma unroll
    for (int rr = 0; rr < 2; rr++) {
        const int pl = (p0 + arow + rr * 64) % PP;
        apy[rr] = pl / WW;
        apx[rr] = pl % WW;
    }

    float4 acc[4][4];
#pragma unroll
    for (int i = 0; i < 4; i++)
#pragma unroll
        for (int j = 0; j < 4; j++) acc[i][j] = make_float4(0.f, 0.f, 0.f, 0.f);

#define CONV_ISSUE(TAP, KB, BUF)                                                     \
    do {                                                                             \
        const int dy = (TAP) / 3 - 1, dx = (TAP) % 3 - 1;                            \
        _Pragma("unroll")                                                            \
        for (int rr = 0; rr < 2; rr++) {                                             \
            const int r = arow + rr * 64;                                            \
            const bool valid = ((unsigned)(apy[rr] + dy) < (unsigned)HH) &&          \
                               ((unsigned)(apx[rr] + dx) < (unsigned)WW);            \
            cpa16(asb[BUF] + (r * 28 + aseg) * 4,                                    \
                  X + (size_t)(p0 + r + dy * WW + dx) * CP + (KB) + aseg, valid);    \
        }                                                                            \
        _Pragma("unroll")                                                            \
        for (int rr = 0; rr < 2; rr++) {                                             \
            const int rb = brow + rr * 8;                                            \
            cpa16(bsb[BUF] + (rb * 136 + bseg) * 4,                                  \
                  Wt + (size_t)((TAP) * CIE + (KB) + rb) * CP + c0 + bseg, true);    \
        }                                                                            \
        cpa_commit();                                                                \
    } while (0)

    CONV_ISSUE(0, 0, 0);
    const int NIT = 9 * (CIE / 16);   // 189
    int buf = 0;
    for (int it = 0; it < NIT; ++it) {
        cpa_wait0();
        __syncthreads();
        if (it + 1 < NIT) {
            const int nit = it + 1;
            const int ntap = nit / (CIE / 16);
            const int nkb = (nit % (CIE / 16)) * 16;
            CONV_ISSUE(ntap, nkb, buf ^ 1);
        }
#pragma unroll
        for (int ks = 0; ks < 16; ks += 8) {
            uint32_t af[4][4], bf[4][2];
#pragma unroll
            for (int i = 0; i < 4; i++) {
                const int mb = m0 + i * 16 + lr;
                af[i][0] = f2u(As[buf][mb][ks + lc4]);
                af[i][1] = f2u(As[buf][mb + 8][ks + lc4]);
                af[i][2] = f2u(As[buf][mb][ks + lc4 + 4]);
                af[i][3] = f2u(As[buf][mb + 8][ks + lc4 + 4]);
            }
#pragma unroll
            for (int j = 0; j < 4; j++) {
                const int nb = n0 + j * 8 + lr;
                bf[j][0] = f2u(Bs[buf][ks + lc4][nb]);
                bf[j][1] = f2u(Bs[buf][ks + lc4 + 4][nb]);
            }
#pragma unroll
            for (int i = 0; i < 4; i++)
#pragma unroll
                for (int j = 0; j < 4; j++)
                    mma_tf32(acc[i][j], af[i][0], af[i][1], af[i][2], af[i][3],
                             bf[j][0], bf[j][1]);
        }
        buf ^= 1;
    }
#undef CONV_ISSUE

#pragma unroll
    for (int i = 0; i < 4; i++) {
        const int r0 = p0 + m0 + i * 16 + lr;
#pragma unroll
        for (int j = 0; j < 4; j++) {
            const int c = c0 + n0 + j * 8 + lc4 * 2;
            const float bv0 = (c < CH) ? bias[c] : 0.f;
            const float bv1 = (c + 1 < CH) ? bias[c + 1] : 0.f;
            float vx = fmaxf(acc[i][j].x + bv0, 0.f);
            float vy = fmaxf(acc[i][j].y + bv1, 0.f);
            float vz = fmaxf(acc[i][j].z + bv0, 0.f);
            float vw = fmaxf(acc[i][j].w + bv1, 0.f);
            if (ADD_RES) {
                const float2 r0v = *(const float2*)&res[(size_t)r0 * CP + c];
                const float2 r1v = *(const float2*)&res[(size_t)(r0 + 8) * CP + c];
                vx += r0v.x; vy += r0v.y; vz += r1v.x; vw += r1v.y;
            } else {
                vx = to_tf32(vx); vy = to_tf32(vy);
                vz = to_tf32(vz); vw = to_tf32(vw);
            }
            *(float2*)&Y[(size_t)r0 * CP + c]       = make_float2(vx, vy);
            *(float2*)&Y[(size_t)(r0 + 8) * CP + c] = make_float2(vz, vw);
        }
    }
}

// ---------------- LayerNorm over 324 channels + NHWC -> NCHW store (both branches) ----
__global__ __launch_bounds__(256) void ln_k(const float* __restrict__ Yin,
                                            const float* __restrict__ g,
                                            const float* __restrict__ bta,
                                            float* __restrict__ out) {
    __shared__ float tile[CH][33];
    const int br = blockIdx.y;
    const int p0 = blockIdx.x * 32;
    const float* Ybr = Yin + (size_t)br * PP * CP;
    const int cbase = br * CH;
    const int warp = threadIdx.x >> 5, lane = threadIdx.x & 31;
#pragma unroll
    for (int r = 0; r < 4; r++) {
        const int lp = warp + r * 8;
        const float* row = Ybr + (size_t)(p0 + lp) * CP;
        float vals[11];
        float s = 0.f, sq = 0.f;
#pragma unroll
        for (int j = 0; j < 11; j++) {
            const int ch = lane + j * 32;
            float v = (ch < CH) ? row[ch] : 0.f;
            vals[j] = v;
            s += v;
            sq += v * v;
        }
#pragma unroll
        for (int o = 16; o; o >>= 1) {
            s += __shfl_xor_sync(0xffffffffu, s, o);
            sq += __shfl_xor_sync(0xffffffffu, sq, o);
        }
        const float mean = s * (1.f / 324.f);
        const float var = sq * (1.f / 324.f) - mean * mean;
        const float inv = rsqrtf(var + 1e-5f);
#pragma unroll
        for (int j = 0; j < 11; j++) {
            const int ch = lane + j * 32;
            if (ch < CH)
                tile[ch][lp] = (vals[j] - mean) * inv * g[ch] + bta[ch];
        }
    }
    __syncthreads();
    const int col = threadIdx.x & 31;
    for (int ch = threadIdx.x >> 5; ch < CH; ch += 8)
        out[(size_t)(cbase + ch) * PP + p0 + col] = tile[ch][col];
}

// ---------------- launch ----------------
extern "C" void kernel_launch(void* const* d_in, const int* in_sizes, int n_in,
                              void* d_out, int out_size) {
    const float* f0  = (const float*)d_in[0];
    const float* f1  = (const float*)d_in[1];
    const float* w1  = (const float*)d_in[2];
    const float* b1  = (const float*)d_in[3];
    const float* w2  = (const float*)d_in[4];
    const float* b2  = (const float*)d_in[5];
    const float* lng = (const float*)d_in[6];
    const float* lnb = (const float*)d_in[7];
    float* out = (float*)d_out;

    float *corr0, *corr1, *f0r, *f1r, *ft, *t1, *t2, *wp1, *wp2;
    cudaGetSymbolAddress((void**)&corr0, g_corr0);
    cudaGetSymbolAddress((void**)&corr1, g_corr1);
    cudaGetSymbolAddress((void**)&f0r, g_f0r);
    cudaGetSymbolAddress((void**)&f1r, g_f1r);
    cudaGetSymbolAddress((void**)&ft, g_feat);
    cudaGetSymbolAddress((void**)&t1, g_t1);
    cudaGetSymbolAddress((void**)&t2, g_t2);
    cudaGetSymbolAddress((void**)&wp1, g_w1);
    cudaGetSymbolAddress((void**)&wp2, g_w2);

    const int n4 = PP * KC / 4;
    // 0,1: tf32 pre-round of f0/f1
    round4_k<<<(n4 + 255) / 256, 256>>>((const float4*)f0, (float4*)f0r);
    round4_k<<<(n4 + 255) / 256, 256>>>((const float4*)f1, (float4*)f1r);
    // 2: weight repack (both sets)
    repack_w<<<dim3((9 * CIE * CP + 255) / 256, 2), 256>>>(w1, w2, wp1, wp2);
    // 3: correlation GEMM writing corr01 and corr10
    gemm_tc<<<dim3(50, 50), 256>>>(f0r, f1r, corr0, corr1);
    // 4: fused pyramid + lookup (both branches)
    pyrlook_k<<<dim3(PP, 2), 256>>>(corr0, corr1, ft);
    // 5,6: convs, both branches batched (M = 12800)
    conv_tc<0><<<dim3(100, 3), 256>>>(ft, wp1, b1, nullptr, t1);
    conv_tc<1><<<dim3(100, 3), 256>>>(t1, wp2, b2, ft, t2);
    // 7: LayerNorm + transpose to NCHW
    ln_k<<<dim3(200, 2), 256>>>(t2, lng, lnb, out);
}

// round 5
// speedup vs baseline: 2.9255x; 1.0373x over previous
#include <cuda_runtime.h>
#include <cstdint>

#define PP 6400
#define HH 80
#define WW 80
#define KC 256      // inner dim of correlation GEMM
#define CH 324      // real channels per direction
#define CP 384      // padded channel stride
#define CIE 336     // ci loop end (324 rounded up to 16)

#define GST 4       // gemm pipeline stages
#define CST 3       // conv pipeline stages

// ---------------- scratch (static device globals; no allocs) ----------------
__device__ float g_corr0[(size_t)PP * PP];   // corr01  (P, 80, 80)
__device__ float g_corr1[(size_t)PP * PP];   // corr10 = corr01^T
__device__ float g_f0r[PP * KC];             // tf32-rounded f0
__device__ float g_f1r[PP * KC];             // tf32-rounded f1
__device__ float g_feat[2 * PP * CP];        // lookup features (tf32), both branches
__device__ float g_t1[2 * PP * CP];
__device__ float g_t2[2 * PP * CP];
__device__ float g_w1[9 * CIE * CP];
__device__ float g_w2[9 * CIE * CP];

// ---------------- helpers ----------------
__device__ __forceinline__ float to_tf32(float x) {
    float y;
    asm("cvt.rna.tf32.f32 %0, %1;" : "=f"(y) : "f"(x));
    return y;
}

__device__ __forceinline__ void mma_tf32(float4& c,
                                         uint32_t a0, uint32_t a1, uint32_t a2, uint32_t a3,
                                         uint32_t b0, uint32_t b1) {
    asm volatile(
        "mma.sync.aligned.m16n8k8.row.col.f32.tf32.tf32.f32 "
        "{%0,%1,%2,%3}, {%4,%5,%6,%7}, {%8,%9}, {%0,%1,%2,%3};"
        : "+f"(c.x), "+f"(c.y), "+f"(c.z), "+f"(c.w)
        : "r"(a0), "r"(a1), "r"(a2), "r"(a3), "r"(b0), "r"(b1));
}

__device__ __forceinline__ uint32_t f2u(float x) { return __float_as_uint(x); }

__device__ __forceinline__ uint32_t su32(const void* p) {
    uint32_t a;
    asm("{ .reg .u64 t; cvta.to.shared.u64 t, %1; cvt.u32.u64 %0, t; }"
        : "=r"(a) : "l"(p));
    return a;
}

__device__ __forceinline__ void cpa16(uint32_t dst, const void* src, bool v) {
    asm volatile("cp.async.cg.shared.global [%0], [%1], 16, %2;"
                 :: "r"(dst), "l"(src), "r"(v ? 16 : 0));
}
__device__ __forceinline__ void cpa_commit() {
    asm volatile("cp.async.commit_group;");
}
template <int N>
__device__ __forceinline__ void cpa_wait() {
    asm volatile("cp.async.wait_group %0;" :: "n"(N));
}

// ---------------- tf32 rounding pass ----------------
__global__ void round4_k(const float4* __restrict__ in, float4* __restrict__ out) {
    const int i = blockIdx.x * blockDim.x + threadIdx.x;
    if (i < PP * KC / 4) {
        float4 v = in[i];
        out[i] = make_float4(to_tf32(v.x), to_tf32(v.y), to_tf32(v.z), to_tf32(v.w));
    }
}

// ---------------- weight repack (both weight sets; tf32-rounded) ----------------
__global__ void repack_w(const float* __restrict__ w1, const float* __restrict__ w2,
                         float* __restrict__ wp1, float* __restrict__ wp2) {
    const int id = blockIdx.x * blockDim.x + threadIdx.x;
    if (id >= 9 * CIE * CP) return;
    const float* w = blockIdx.y ? w2 : w1;
    float* wp = blockIdx.y ? wp2 : wp1;
    const int co = id % CP;
    const int t = id / CP;
    const int ci = t % CIE;
    const int tap = t / CIE;
    wp[id] = (ci < CH && co < CH) ? to_tf32(w[((size_t)(tap * CH + ci)) * CH + co]) : 0.f;
}

// ---------------- tensor-core GEMM writing C and C^T ----------------
// 128x128 tile, BK=16, GST-stage cp.async pipeline; 8 warps (2x4), warp tile 64x32.
// Dynamic smem: GST*(16*136)*2 floats.
__global__ __launch_bounds__(256) void gemm_tc(const float* __restrict__ A,
                                               const float* __restrict__ B,
                                               float* __restrict__ C0,
                                               float* __restrict__ C1) {
    extern __shared__ float sm[];
    float* Asb = sm;                       // GST stages of [16][136]
    float* Bsb = sm + GST * 2176;
    const uint32_t asu = su32(Asb);
    const uint32_t bsu = su32(Bsb);

    const int tid = threadIdx.x;
    const int p0 = blockIdx.y * 128;
    const int q0 = blockIdx.x * 128;
    const int warp = tid >> 5, lane = tid & 31;
    const int wm = warp >> 2, wn = warp & 3;   // 2 x 4
    const int m0 = wm * 64, n0 = wn * 32;
    const int lr = lane >> 2, lc4 = lane & 3;
    const int krow = tid >> 5;              // 0..7 (loads rows krow, krow+8)
    const int seg = (tid & 31) * 4;         // 0..124

    float4 acc[4][4];
#pragma unroll
    for (int i = 0; i < 4; i++)
#pragma unroll
        for (int j = 0; j < 4; j++) acc[i][j] = make_float4(0.f, 0.f, 0.f, 0.f);

    const float* Ap = A + p0 + seg;
    const float* Bp = B + q0 + seg;

#define GEMM_ISSUE(SLAB, BUF)                                                          \
    do {                                                                               \
        const int koff = (SLAB) * 16;                                                  \
        _Pragma("unroll")                                                              \
        for (int rr = 0; rr < 2; rr++) {                                               \
            const int r = krow + rr * 8;                                               \
            cpa16(asu + ((BUF) * 2176 + r * 136 + seg) * 4,                            \
                  Ap + (size_t)(koff + r) * PP, true);                                 \
            cpa16(bsu + ((BUF) * 2176 + r * 136 + seg) * 4,                            \
                  Bp + (size_t)(koff + r) * PP, true);                                 \
        }                                                                              \
        cpa_commit();                                                                  \
    } while (0)

    const int NSLAB = KC / 16;   // 16
#pragma unroll
    for (int s = 0; s < GST - 1; s++) GEMM_ISSUE(s, s);

    for (int it = 0; it < NSLAB; ++it) {
        cpa_wait<GST - 2>();
        __syncthreads();
        if (it + GST - 1 < NSLAB) GEMM_ISSUE(it + GST - 1, (it + GST - 1) % GST);
        const float* Asf = Asb + (it % GST) * 2176;
        const float* Bsf = Bsb + (it % GST) * 2176;
#pragma unroll
        for (int ks = 0; ks < 16; ks += 8) {
            uint32_t af[4][4], bf[4][2];
#pragma unroll
            for (int i = 0; i < 4; i++) {
                const int mb = m0 + i * 16 + lr;
                af[i][0] = f2u(Asf[(ks + lc4) * 136 + mb]);
                af[i][1] = f2u(Asf[(ks + lc4) * 136 + mb + 8]);
                af[i][2] = f2u(Asf[(ks + lc4 + 4) * 136 + mb]);
                af[i][3] = f2u(Asf[(ks + lc4 + 4) * 136 + mb + 8]);
            }
#pragma unroll
            for (int j = 0; j < 4; j++) {
                const int nb = n0 + j * 8 + lr;
                bf[j][0] = f2u(Bsf[(ks + lc4) * 136 + nb]);
                bf[j][1] = f2u(Bsf[(ks + lc4 + 4) * 136 + nb]);
            }
#pragma unroll
            for (int i = 0; i < 4; i++)
#pragma unroll
                for (int j = 0; j < 4; j++)
                    mma_tf32(acc[i][j], af[i][0], af[i][1], af[i][2], af[i][3],
                             bf[j][0], bf[j][1]);
        }
    }
#undef GEMM_ISSUE

#pragma unroll
    for (int i = 0; i < 4; i++) {
        const int r = p0 + m0 + i * 16 + lr;
#pragma unroll
        for (int j = 0; j < 4; j++) {
            const int c = q0 + n0 + j * 8 + lc4 * 2;
            *(float2*)&C0[(size_t)r * PP + c]       = make_float2(acc[i][j].x, acc[i][j].y);
            *(float2*)&C0[(size_t)(r + 8) * PP + c] = make_float2(acc[i][j].z, acc[i][j].w);
            C1[(size_t)c * PP + r]           = acc[i][j].x;
            C1[(size_t)(c + 1) * PP + r]     = acc[i][j].y;
            C1[(size_t)c * PP + r + 8]       = acc[i][j].z;
            C1[(size_t)(c + 1) * PP + r + 8] = acc[i][j].w;
        }
    }
}

// ---------------- fused pyramid + lookup (tf32-rounded output) ----------------
__global__ __launch_bounds__(256) void pyrlook_k(const float* __restrict__ corr0,
                                                 const float* __restrict__ corr1,
                                                 float* __restrict__ feat) {
    __shared__ float L0[6400];
    __shared__ float L1[1600];
    __shared__ float L2[400];
    __shared__ float L3[100];
    const int p = blockIdx.x;
    const int br = blockIdx.y;
    const float* corr = br ? corr1 : corr0;

    const float4* src = (const float4*)(corr + (size_t)p * PP);
    float4* d0 = (float4*)L0;
    for (int i = threadIdx.x; i < 1600; i += 256) d0[i] = src[i];
    __syncthreads();
    for (int i = threadIdx.x; i < 1600; i += 256) {
        const int y = i / 40, x = i % 40;
        const float* m = L0 + y * 160 + x * 2;
        L1[i] = 0.25f * (m[0] + m[1] + m[80] + m[81]);
    }
    __syncthreads();
    for (int i = threadIdx.x; i < 400; i += 256) {
        const int y = i / 20, x = i % 20;
        const float* m = L1 + y * 80 + x * 2;
        L2[i] = 0.25f * (m[0] + m[1] + m[40] + m[41]);
    }
    __syncthreads();
    for (int i = threadIdx.x; i < 100; i += 256) {
        const int y = i / 10, x = i % 10;
        const float* m = L2 + y * 40 + x * 2;
        L3[i] = 0.25f * (m[0] + m[1] + m[20] + m[21]);
    }
    __syncthreads();

    const int px = p % WW, py = p / WW;
    float* out = feat + ((size_t)br * PP + p) * CP;
    for (int ch = threadIdx.x; ch < CP; ch += 256) {
        float v = 0.f;
        if (ch < CH) {
            const int lvl = ch / 81;
            const int off = ch % 81;
            const int dx = off / 9 - 4;
            const int dy = off % 9 - 4;
            const float* base;
            int hl;
            switch (lvl) {
                case 0: base = L0; hl = 80; break;
                case 1: base = L1; hl = 40; break;
                case 2: base = L2; hl = 20; break;
                default: base = L3; hl = 10; break;
            }
            const int wl = hl;
            const float s = (float)(1 << lvl);
            const float cx = (2.f * px + 1.f) / (2.f * s) - 0.5f + (float)dx;
            const float cy = (2.f * py + 1.f) / (2.f * s) - 0.5f + (float)dy;
            const float x0f = floorf(cx), y0f = floorf(cy);
            const int ix = (int)x0f, iy = (int)y0f;
            const float fx = cx - x0f, fy = cy - y0f;
            float v00 = 0.f, v10 = 0.f, v01 = 0.f, v11 = 0.f;
            const bool xv0 = (ix >= 0) & (ix < wl);
            const bool xv1 = (ix + 1 >= 0) & (ix + 1 < wl);
            const bool yv0 = (iy >= 0) & (iy < hl);
            const bool yv1 = (iy + 1 >= 0) & (iy + 1 < hl);
            if (yv0) {
                if (xv0) v00 = base[iy * wl + ix];
                if (xv1) v10 = base[iy * wl + ix + 1];
            }
            if (yv1) {
                if (xv0) v01 = base[(iy + 1) * wl + ix];
                if (xv1) v11 = base[(iy + 1) * wl + ix + 1];
            }
            v = v00 * (1.f - fx) * (1.f - fy) + v10 * fx * (1.f - fy)
              + v01 * (1.f - fx) * fy + v11 * fx * fy;
        }
        out[ch] = to_tf32(v);
    }
}

// ---------------- 3x3 conv as implicit GEMM, CST-stage cp.async pipeline ----------------
// M=12800 (BM=128), N=384 (BN=128), K=9 taps x 336, BK=16.
// 8 warps (2x4), warp tile 64x32. Epilogue relu(acc+bias) [+res].
// Dynamic smem: CST*(128*28 + 16*136) floats.
template <int ADD_RES>
__global__ __launch_bounds__(256) void conv_tc(const float* __restrict__ X,
                                               const float* __restrict__ Wt,
                                               const float* __restrict__ bias,
                                               const float* __restrict__ res,
                                               float* __restrict__ Y) {
    extern __shared__ float sm[];
    float* Asb = sm;                        // CST stages of [128][28]
    float* Bsb = sm + CST * 3584;           // CST stages of [16][136]
    const uint32_t asu = su32(Asb);
    const uint32_t bsu = su32(Bsb);

    const int tid = threadIdx.x;
    const int p0 = blockIdx.x * 128;
    const int c0 = blockIdx.y * 128;
    const int warp = tid >> 5, lane = tid & 31;
    const int wm = warp >> 2, wn = warp & 3;   // 2 x 4
    const int m0 = wm * 64, n0 = wn * 32;
    const int lr = lane >> 2, lc4 = lane & 3;

    // A loader: rows arow, arow+64; 16-float slab split in 4 segs
    const int arow = tid >> 2;
    const int aseg = (tid & 3) * 4;
    // B loader: rows brow, brow+8; 128 cols in 32 segs
    const int brow = tid >> 5;
    const int bseg = (tid & 31) * 4;

    int apy[2], apx[2];
#pragma unroll
    for (int rr = 0; rr < 2; rr++) {
        const int pl = (p0 + arow + rr * 64) % PP;
        apy[rr] = pl / WW;
        apx[rr] = pl % WW;
    }

    float4 acc[4][4];
#pragma unroll
    for (int i = 0; i < 4; i++)
#pragma unroll
        for (int j = 0; j < 4; j++) acc[i][j] = make_float4(0.f, 0.f, 0.f, 0.f);

#define CONV_ISSUE(SLAB, BUF)                                                        \
    do {                                                                             \
        const int tap_ = (SLAB) / (CIE / 16);                                        \
        const int kb_ = ((SLAB) % (CIE / 16)) * 16;                                  \
        const int dy = tap_ / 3 - 1, dx = tap_ % 3 - 1;                              \
        _Pragma("unroll")                                                            \
        for (int rr = 0; rr < 2; rr++) {                                             \
            const int r = arow + rr * 64;                                            \
            const bool valid = ((unsigned)(apy[rr] + dy) < (unsigned)HH) &&          \
                               ((unsigned)(apx[rr] + dx) < (unsigned)WW);            \
            cpa16(asu + ((BUF) * 3584 + r * 28 + aseg) * 4,                          \
                  X + (size_t)(p0 + r + dy * WW + dx) * CP + kb_ + aseg, valid);     \
        }                                                                            \
        _Pragma("unroll")                                                            \
        for (int rr = 0; rr < 2; rr++) {                                             \
            const int rb = brow + rr * 8;                                            \
            cpa16(bsu + ((BUF) * 2176 + rb * 136 + bseg) * 4,                        \
                  Wt + (size_t)(tap_ * CIE + kb_ + rb) * CP + c0 + bseg, true);      \
        }                                                                            \
        cpa_commit();                                                                \
    } while (0)

    const int NIT = 9 * (CIE / 16);   // 189
#pragma unroll
    for (int s = 0; s < CST - 1; s++) CONV_ISSUE(s, s);

    for (int it = 0; it < NIT; ++it) {
        cpa_wait<CST - 2>();
        __syncthreads();
        if (it + CST - 1 < NIT) CONV_ISSUE(it + CST - 1, (it + CST - 1) % CST);
        const float* Asf = Asb + (it % CST) * 3584;
        const float* Bsf = Bsb + (it % CST) * 2176;
#pragma unroll
        for (int ks = 0; ks < 16; ks += 8) {
            uint32_t af[4][4], bf[4][2];
#pragma unroll
            for (int i = 0; i < 4; i++) {
                const int mb = m0 + i * 16 + lr;
                af[i][0] = f2u(Asf[mb * 28 + ks + lc4]);
                af[i][1] = f2u(Asf[(mb + 8) * 28 + ks + lc4]);
                af[i][2] = f2u(Asf[mb * 28 + ks + lc4 + 4]);
                af[i][3] = f2u(Asf[(mb + 8) * 28 + ks + lc4 + 4]);
            }
#pragma unroll
            for (int j = 0; j < 4; j++) {
                const int nb = n0 + j * 8 + lr;
                bf[j][0] = f2u(Bsf[(ks + lc4) * 136 + nb]);
                bf[j][1] = f2u(Bsf[(ks + lc4 + 4) * 136 + nb]);
            }
#pragma unroll
            for (int i = 0; i < 4; i++)
#pragma unroll
                for (int j = 0; j < 4; j++)
                    mma_tf32(acc[i][j], af[i][0], af[i][1], af[i][2], af[i][3],
                             bf[j][0], bf[j][1]);
        }
    }
#undef CONV_ISSUE

#pragma unroll
    for (int i = 0; i < 4; i++) {
        const int r0 = p0 + m0 + i * 16 + lr;
#pragma unroll
        for (int j = 0; j < 4; j++) {
            const int c = c0 + n0 + j * 8 + lc4 * 2;
            const float bv0 = (c < CH) ? bias[c] : 0.f;
            const float bv1 = (c + 1 < CH) ? bias[c + 1] : 0.f;
            float vx = fmaxf(acc[i][j].x + bv0, 0.f);
            float vy = fmaxf(acc[i][j].y + bv1, 0.f);
            float vz = fmaxf(acc[i][j].z + bv0, 0.f);
            float vw = fmaxf(acc[i][j].w + bv1, 0.f);
            if (ADD_RES) {
                const float2 r0v = *(const float2*)&res[(size_t)r0 * CP + c];
                const float2 r1v = *(const float2*)&res[(size_t)(r0 + 8) * CP + c];
                vx += r0v.x; vy += r0v.y; vz += r1v.x; vw += r1v.y;
            } else {
                vx = to_tf32(vx); vy = to_tf32(vy);
                vz = to_tf32(vz); vw = to_tf32(vw);
            }
            *(float2*)&Y[(size_t)r0 * CP + c]       = make_float2(vx, vy);
            *(float2*)&Y[(size_t)(r0 + 8) * CP + c] = make_float2(vz, vw);
        }
    }
}

// ---------------- LayerNorm over 324 channels + NHWC -> NCHW store (both branches) ----
__global__ __launch_bounds__(256) void ln_k(const float* __restrict__ Yin,
                                            const float* __restrict__ g,
                                            const float* __restrict__ bta,
                                            float* __restrict__ out) {
    __shared__ float tile[CH][33];
    const int br = blockIdx.y;
    const int p0 = blockIdx.x * 32;
    const float* Ybr = Yin + (size_t)br * PP * CP;
    const int cbase = br * CH;
    const int warp = threadIdx.x >> 5, lane = threadIdx.x & 31;
#pragma unroll
    for (int r = 0; r < 4; r++) {
        const int lp = warp + r * 8;
        const float* row = Ybr + (size_t)(p0 + lp) * CP;
        float vals[11];
        float s = 0.f, sq = 0.f;
#pragma unroll
        for (int j = 0; j < 11; j++) {
            const int ch = lane + j * 32;
            float v = (ch < CH) ? row[ch] : 0.f;
            vals[j] = v;
            s += v;
            sq += v * v;
        }
#pragma unroll
        for (int o = 16; o; o >>= 1) {
            s += __shfl_xor_sync(0xffffffffu, s, o);
            sq += __shfl_xor_sync(0xffffffffu, sq, o);
        }
        const float mean = s * (1.f / 324.f);
        const float var = sq * (1.f / 324.f) - mean * mean;
        const float inv = rsqrtf(var + 1e-5f);
#pragma unroll
        for (int j = 0; j < 11; j++) {
            const int ch = lane + j * 32;
            if (ch < CH)
                tile[ch][lp] = (vals[j] - mean) * inv * g[ch] + bta[ch];
        }
    }
    __syncthreads();
    const int col = threadIdx.x & 31;
    for (int ch = threadIdx.x >> 5; ch < CH; ch += 8)
        out[(size_t)(cbase + ch) * PP + p0 + col] = tile[ch][col];
}

// ---------------- launch ----------------
extern "C" void kernel_launch(void* const* d_in, const int* in_sizes, int n_in,
                              void* d_out, int out_size) {
    const float* f0  = (const float*)d_in[0];
    const float* f1  = (const float*)d_in[1];
    const float* w1  = (const float*)d_in[2];
    const float* b1  = (const float*)d_in[3];
    const float* w2  = (const float*)d_in[4];
    const float* b2  = (const float*)d_in[5];
    const float* lng = (const float*)d_in[6];
    const float* lnb = (const float*)d_in[7];
    float* out = (float*)d_out;

    float *corr0, *corr1, *f0r, *f1r, *ft, *t1, *t2, *wp1, *wp2;
    cudaGetSymbolAddress((void**)&corr0, g_corr0);
    cudaGetSymbolAddress((void**)&corr1, g_corr1);
    cudaGetSymbolAddress((void**)&f0r, g_f0r);
    cudaGetSymbolAddress((void**)&f1r, g_f1r);
    cudaGetSymbolAddress((void**)&ft, g_feat);
    cudaGetSymbolAddress((void**)&t1, g_t1);
    cudaGetSymbolAddress((void**)&t2, g_t2);
    cudaGetSymbolAddress((void**)&wp1, g_w1);
    cudaGetSymbolAddress((void**)&wp2, g_w2);

    const int gemm_smem = GST * 2176 * 2 * 4;                  // ~69.6 KB
    const int conv_smem = CST * (3584 + 2176) * 4;             // ~69.1 KB
    cudaFuncSetAttribute(gemm_tc, cudaFuncAttributeMaxDynamicSharedMemorySize, gemm_smem);
    cudaFuncSetAttribute(conv_tc<0>, cudaFuncAttributeMaxDynamicSharedMemorySize, conv_smem);
    cudaFuncSetAttribute(conv_tc<1>, cudaFuncAttributeMaxDynamicSharedMemorySize, conv_smem);

    const int n4 = PP * KC / 4;
    // 0,1: tf32 pre-round of f0/f1
    round4_k<<<(n4 + 255) / 256, 256>>>((const float4*)f0, (float4*)f0r);
    round4_k<<<(n4 + 255) / 256, 256>>>((const float4*)f1, (float4*)f1r);
    // 2: weight repack (both sets)
    repack_w<<<dim3((9 * CIE * CP + 255) / 256, 2), 256>>>(w1, w2, wp1, wp2);
    // 3: correlation GEMM writing corr01 and corr10
    gemm_tc<<<dim3(50, 50), 256, gemm_smem>>>(f0r, f1r, corr0, corr1);
    // 4: fused pyramid + lookup (both branches)
    pyrlook_k<<<dim3(PP, 2), 256>>>(corr0, corr1, ft);
    // 5,6: convs, both branches batched (M = 12800)
    conv_tc<0><<<dim3(100, 3), 256, conv_smem>>>(ft, wp1, b1, nullptr, t1);
    conv_tc<1><<<dim3(100, 3), 256, conv_smem>>>(t1, wp2, b2, ft, t2);
    // 7: LayerNorm + transpose to NCHW
    ln_k<<<dim3(200, 2), 256>>>(t2, lng, lnb, out);
}